// round 1
// baseline (speedup 1.0000x reference)
#include <cuda_runtime.h>
#include <cuda_bf16.h>
#include <math.h>

// Problem constants
#define DIMM 5120
#define NHEADS 40
#define HDIM 128
#define BB 2
#define LL 1024
#define TOKENS (BB*LL)          // 2048
#define QKVDIM (3*DIMM)         // 15360
#define SCALE 0.08838834764831845f   // 128^-0.5
#define EPS 1e-6f

// -------- scratch (static device globals; no runtime allocation) --------
__device__ float g_qkv[(size_t)TOKENS * QKVDIM];          // 125.8 MB
__device__ float g_q[(size_t)TOKENS * DIMM];              // 41.9 MB (post norm+rope)
__device__ float g_k[(size_t)TOKENS * DIMM];              // 41.9 MB
__device__ float g_scores[(size_t)BB * NHEADS * LL * LL]; // 335.5 MB
__device__ float g_o[(size_t)TOKENS * DIMM];              // 41.9 MB

// ============================================================
// Kernel 1/6: classic 128x128x8 SGEMM with bias.
// C[M,N] = A[M,K] * B[K,N] + bias[N].  M%128==0, N%128==0, K%8==0.
// 256 threads, each computes an 8x8 micro-tile.
// ============================================================
__global__ __launch_bounds__(256) void sgemm_bias(
    const float* __restrict__ A, const float* __restrict__ B,
    const float* __restrict__ bias, float* __restrict__ C,
    int M, int N, int K)
{
    __shared__ float As[8][128];
    __shared__ float Bs[8][128];

    const int tid = threadIdx.x;
    const int bx = blockIdx.x;   // N tile
    const int by = blockIdx.y;   // M tile
    const int tx = tid & 15;     // 0..15
    const int ty = tid >> 4;     // 0..15

    // A tile load mapping: 128 rows x 8 cols, float4 along K
    const int arow = tid >> 1;          // 0..127
    const int acol = (tid & 1) * 4;     // 0 or 4
    // B tile load mapping: 8 rows x 128 cols, float4 along N
    const int brow = tid >> 5;          // 0..7
    const int bcol = (tid & 31) * 4;    // 0..124

    const float* Ap = A + (size_t)(by * 128 + arow) * K + acol;
    const float* Bp = B + (size_t)brow * N + bx * 128 + bcol;

    float acc[8][8];
#pragma unroll
    for (int i = 0; i < 8; i++)
#pragma unroll
        for (int j = 0; j < 8; j++) acc[i][j] = 0.f;

    for (int k0 = 0; k0 < K; k0 += 8) {
        float4 av = *(const float4*)(Ap + k0);
        As[acol + 0][arow] = av.x;
        As[acol + 1][arow] = av.y;
        As[acol + 2][arow] = av.z;
        As[acol + 3][arow] = av.w;
        float4 bv = *(const float4*)(Bp + (size_t)k0 * N);
        *(float4*)&Bs[brow][bcol] = bv;
        __syncthreads();

#pragma unroll
        for (int kk = 0; kk < 8; kk++) {
            float a[8], b[8];
            *(float4*)&a[0] = *(const float4*)&As[kk][ty * 8];
            *(float4*)&a[4] = *(const float4*)&As[kk][ty * 8 + 4];
            *(float4*)&b[0] = *(const float4*)&Bs[kk][tx * 8];
            *(float4*)&b[4] = *(const float4*)&Bs[kk][tx * 8 + 4];
#pragma unroll
            for (int i = 0; i < 8; i++)
#pragma unroll
                for (int j = 0; j < 8; j++)
                    acc[i][j] = fmaf(a[i], b[j], acc[i][j]);
        }
        __syncthreads();
    }

    // epilogue
#pragma unroll
    for (int j = 0; j < 8; j++) {
        int col = bx * 128 + tx * 8 + j;
        float bb2 = bias[col];
#pragma unroll
        for (int i = 0; i < 8; i++) {
            int row = by * 128 + ty * 8 + i;
            C[(size_t)row * N + col] = acc[i][j] + bb2;
        }
    }
}

// ============================================================
// Kernel 2/6: fused RMSNorm (over full DIM) + gain + RoPE for q and k.
// One block (256 thr) per token. Reads g_qkv, writes g_q, g_k.
// ============================================================
__global__ __launch_bounds__(256) void rmsrope_kernel(
    const float* __restrict__ cosb, const float* __restrict__ sinb,
    const float* __restrict__ gq, const float* __restrict__ gk)
{
    const int t = blockIdx.x;
    const int tid = threadIdx.x;
    const float* base = g_qkv + (size_t)t * QKVDIM;

    float sq = 0.f, sk = 0.f;
    for (int i = tid; i < DIMM; i += 256) {
        float a = base[i];         sq = fmaf(a, a, sq);
        float b = base[DIMM + i];  sk = fmaf(b, b, sk);
    }
    __shared__ float r1[256], r2[256];
    r1[tid] = sq; r2[tid] = sk;
    __syncthreads();
    for (int s = 128; s > 0; s >>= 1) {
        if (tid < s) { r1[tid] += r1[tid + s]; r2[tid] += r2[tid + s]; }
        __syncthreads();
    }
    const float rq = rsqrtf(r1[0] / (float)DIMM + EPS);
    const float rk = rsqrtf(r2[0] / (float)DIMM + EPS);

    const int l = t & (LL - 1);
    const float* cl = cosb + (size_t)l * HDIM;
    const float* sl = sinb + (size_t)l * HDIM;
    float* qo = g_q + (size_t)t * DIMM;
    float* ko = g_k + (size_t)t * DIMM;

    for (int p = tid; p < DIMM / 2; p += 256) {
        int d = 2 * p;
        int hd = d & (HDIM - 1);
        float c = cl[hd];       // cos at even index
        float s = sl[hd + 1];   // sin at odd index
        float x0 = base[d]     * rq * gq[d];
        float x1 = base[d + 1] * rq * gq[d + 1];
        qo[d]     = x0 * c - x1 * s;
        qo[d + 1] = x0 * s + x1 * c;
        float y0 = base[DIMM + d]     * rk * gk[d];
        float y1 = base[DIMM + d + 1] * rk * gk[d + 1];
        ko[d]     = y0 * c - y1 * s;
        ko[d + 1] = y0 * s + y1 * c;
    }
}

// ============================================================
// Kernel 3/6: scores[bh, m, n] = SCALE * sum_d q[b,m,h,d] * k[b,n,h,d]
// Batched 64x64x16 A*B^T GEMM, strided rows (5120). grid (16,16,80).
// ============================================================
__global__ __launch_bounds__(256) void scores_kernel()
{
    const int bh = blockIdx.z;
    const int b = bh / NHEADS, h = bh % NHEADS;
    const float* qb = g_q + (size_t)b * LL * DIMM + h * HDIM;
    const float* kb = g_k + (size_t)b * LL * DIMM + h * HDIM;

    __shared__ float As[16][64];
    __shared__ float Bs[16][64];

    const int tid = threadIdx.x;
    const int tx = tid & 15, ty = tid >> 4;
    const int lrow = tid >> 2;          // 0..63
    const int lcol = (tid & 3) * 4;     // 0..12
    const int m0 = blockIdx.y * 64, n0 = blockIdx.x * 64;

    float acc[4][4];
#pragma unroll
    for (int i = 0; i < 4; i++)
#pragma unroll
        for (int j = 0; j < 4; j++) acc[i][j] = 0.f;

    for (int k0 = 0; k0 < HDIM; k0 += 16) {
        float4 av = *(const float4*)(qb + (size_t)(m0 + lrow) * DIMM + k0 + lcol);
        As[lcol + 0][lrow] = av.x; As[lcol + 1][lrow] = av.y;
        As[lcol + 2][lrow] = av.z; As[lcol + 3][lrow] = av.w;
        float4 bv = *(const float4*)(kb + (size_t)(n0 + lrow) * DIMM + k0 + lcol);
        Bs[lcol + 0][lrow] = bv.x; Bs[lcol + 1][lrow] = bv.y;
        Bs[lcol + 2][lrow] = bv.z; Bs[lcol + 3][lrow] = bv.w;
        __syncthreads();
#pragma unroll
        for (int kk = 0; kk < 16; kk++) {
            float a[4], bq[4];
            *(float4*)a  = *(const float4*)&As[kk][ty * 4];
            *(float4*)bq = *(const float4*)&Bs[kk][tx * 4];
#pragma unroll
            for (int i = 0; i < 4; i++)
#pragma unroll
                for (int j = 0; j < 4; j++)
                    acc[i][j] = fmaf(a[i], bq[j], acc[i][j]);
        }
        __syncthreads();
    }

    float* srow = g_scores + (size_t)bh * LL * LL;
#pragma unroll
    for (int i = 0; i < 4; i++)
#pragma unroll
        for (int j = 0; j < 4; j++)
            srow[(size_t)(m0 + ty * 4 + i) * LL + n0 + tx * 4 + j] = acc[i][j] * SCALE;
}

// ============================================================
// Kernel 4/6: softmax over last dim (1024). One block per row.
// ============================================================
__global__ __launch_bounds__(256) void softmax_kernel()
{
    __shared__ float red[256];
    float* row = g_scores + (size_t)blockIdx.x * LL;
    const int tid = threadIdx.x;

    float4 v = ((float4*)row)[tid];
    float m = fmaxf(fmaxf(v.x, v.y), fmaxf(v.z, v.w));
    red[tid] = m;
    __syncthreads();
    for (int s = 128; s > 0; s >>= 1) {
        if (tid < s) red[tid] = fmaxf(red[tid], red[tid + s]);
        __syncthreads();
    }
    m = red[0];
    __syncthreads();

    v.x = expf(v.x - m); v.y = expf(v.y - m);
    v.z = expf(v.z - m); v.w = expf(v.w - m);
    red[tid] = v.x + v.y + v.z + v.w;
    __syncthreads();
    for (int s = 128; s > 0; s >>= 1) {
        if (tid < s) red[tid] += red[tid + s];
        __syncthreads();
    }
    float inv = 1.f / red[0];
    v.x *= inv; v.y *= inv; v.z *= inv; v.w *= inv;
    ((float4*)row)[tid] = v;
}

// ============================================================
// Kernel 5/6: o[b,m,h,d] = sum_k P[bh,m,k] * v[b,k,h,d]
// V read directly from g_qkv (offset 2*DIM, row stride QKVDIM).
// Batched 64x64x16 GEMM. grid (2,16,80).
// ============================================================
__global__ __launch_bounds__(256) void pv_kernel()
{
    const int bh = blockIdx.z;
    const int b = bh / NHEADS, h = bh % NHEADS;
    const float* P = g_scores + (size_t)bh * LL * LL;
    const float* vb = g_qkv + (size_t)b * LL * QKVDIM + 2 * DIMM + h * HDIM;

    __shared__ float Ps[16][64];
    __shared__ float Vs[16][64];

    const int tid = threadIdx.x;
    const int tx = tid & 15, ty = tid >> 4;
    const int prow = tid >> 2;          // 0..63
    const int pcol = (tid & 3) * 4;     // 0..12
    const int vrow = tid >> 4;          // 0..15
    const int vcol = (tid & 15) * 4;    // 0..60
    const int m0 = blockIdx.y * 64, n0 = blockIdx.x * 64;

    float acc[4][4];
#pragma unroll
    for (int i = 0; i < 4; i++)
#pragma unroll
        for (int j = 0; j < 4; j++) acc[i][j] = 0.f;

    for (int k0 = 0; k0 < LL; k0 += 16) {
        float4 pv4 = *(const float4*)(P + (size_t)(m0 + prow) * LL + k0 + pcol);
        Ps[pcol + 0][prow] = pv4.x; Ps[pcol + 1][prow] = pv4.y;
        Ps[pcol + 2][prow] = pv4.z; Ps[pcol + 3][prow] = pv4.w;
        float4 vv = *(const float4*)(vb + (size_t)(k0 + vrow) * QKVDIM + n0 + vcol);
        *(float4*)&Vs[vrow][vcol] = vv;
        __syncthreads();
#pragma unroll
        for (int kk = 0; kk < 16; kk++) {
            float a[4], bq[4];
            *(float4*)a  = *(const float4*)&Ps[kk][ty * 4];
            *(float4*)bq = *(const float4*)&Vs[kk][tx * 4];
#pragma unroll
            for (int i = 0; i < 4; i++)
#pragma unroll
                for (int j = 0; j < 4; j++)
                    acc[i][j] = fmaf(a[i], bq[j], acc[i][j]);
        }
        __syncthreads();
    }

#pragma unroll
    for (int i = 0; i < 4; i++)
#pragma unroll
        for (int j = 0; j < 4; j++)
            g_o[(size_t)(b * LL + m0 + ty * 4 + i) * DIMM + h * HDIM + n0 + tx * 4 + j]
                = acc[i][j];
}

// ============================================================
// launch
// ============================================================
extern "C" void kernel_launch(void* const* d_in, const int* in_sizes, int n_in,
                              void* d_out, int out_size)
{
    const float* x     = (const float*)d_in[0];
    const float* cosb  = (const float*)d_in[1];
    const float* sinb  = (const float*)d_in[2];
    const float* Wqkv  = (const float*)d_in[3];
    const float* bqkv  = (const float*)d_in[4];
    const float* gq    = (const float*)d_in[5];
    const float* gk    = (const float*)d_in[6];
    const float* Wout  = (const float*)d_in[7];
    const float* bout  = (const float*)d_in[8];
    float* out = (float*)d_out;

    void* p_qkv; cudaGetSymbolAddress(&p_qkv, g_qkv);
    void* p_o;   cudaGetSymbolAddress(&p_o, g_o);

    // 1) QKV projection: [2048,5120] x [5120,15360] + b
    sgemm_bias<<<dim3(QKVDIM / 128, TOKENS / 128), 256>>>(
        x, Wqkv, bqkv, (float*)p_qkv, TOKENS, QKVDIM, DIMM);

    // 2) RMSNorm + gain + RoPE for q,k
    rmsrope_kernel<<<TOKENS, 256>>>(cosb, sinb, gq, gk);

    // 3) scores = scale * q k^T  (per b,h)
    scores_kernel<<<dim3(LL / 64, LL / 64, BB * NHEADS), 256>>>();

    // 4) softmax over keys
    softmax_kernel<<<BB * NHEADS * LL, 256>>>();

    // 5) o = P V
    pv_kernel<<<dim3(HDIM / 64, LL / 64, BB * NHEADS), 256>>>();

    // 6) out projection: [2048,5120] x [5120,5120] + b
    sgemm_bias<<<dim3(DIMM / 128, TOKENS / 128), 256>>>(
        (const float*)p_o, Wout, bout, out, TOKENS, DIMM, DIMM);
}

// round 3
// speedup vs baseline: 1.7735x; 1.7735x over previous
#include <cuda_runtime.h>
#include <cuda_bf16.h>
#include <math.h>
#include <stdint.h>

// Problem constants
#define DIMM 5120
#define NHEADS 40
#define HDIM 128
#define BB 2
#define LL 1024
#define TOKENS (BB*LL)          // 2048
#define QKVDIM (3*DIMM)         // 15360
#define SCALE 0.08838834764831845f
#define EPS 1e-6f

// -------- scratch (static device globals; no runtime allocation) --------
__device__ float g_qkv[(size_t)TOKENS * QKVDIM];          // 125.8 MB
__device__ float g_q[(size_t)TOKENS * DIMM];
__device__ float g_k[(size_t)TOKENS * DIMM];
__device__ float g_scores[(size_t)BB * NHEADS * LL * LL]; // 335.5 MB
__device__ float g_o[(size_t)TOKENS * DIMM];
__device__ float g_wq[(size_t)QKVDIM * DIMM];             // W_qkv^T tf32 [N,K]
__device__ float g_wo[(size_t)DIMM * DIMM];               // W_out^T tf32 [N,K]
__device__ float g_x[(size_t)TOKENS * DIMM];              // x tf32-rounded

// ============================================================
// helpers
// ============================================================
__device__ __forceinline__ uint32_t smem_u32(const void* p) {
    uint32_t a;
    asm("{ .reg .u64 t; cvta.to.shared.u64 t, %1; cvt.u32.u64 %0, t; }" : "=r"(a) : "l"(p));
    return a;
}
__device__ __forceinline__ float tf32r(float x) {
    float y; asm("cvt.rna.tf32.f32 %0, %1;" : "=f"(y) : "f"(x)); return y;
}
__device__ __forceinline__ void cpa16(uint32_t dst, const void* src) {
    asm volatile("cp.async.cg.shared.global [%0], [%1], 16;" :: "r"(dst), "l"(src));
}
#define CPA_COMMIT() asm volatile("cp.async.commit_group;" ::: "memory")
#define CPA_WAIT1()  asm volatile("cp.async.wait_group 1;" ::: "memory")
#define CPA_WAIT0()  asm volatile("cp.async.wait_group 0;" ::: "memory")

// m16n8k8 tf32 mma: A/B operands are .b32 regs, accum .f32
__device__ __forceinline__ void mma1688(float* d, const uint32_t* a, const uint32_t* b) {
    asm volatile(
        "mma.sync.aligned.m16n8k8.row.col.f32.tf32.tf32.f32 "
        "{%0,%1,%2,%3}, {%4,%5,%6,%7}, {%8,%9}, {%0,%1,%2,%3};"
        : "+f"(d[0]), "+f"(d[1]), "+f"(d[2]), "+f"(d[3])
        : "r"(a[0]), "r"(a[1]), "r"(a[2]), "r"(a[3]), "r"(b[0]), "r"(b[1]));
}

// ============================================================
// tf32 mma.sync GEMM: C[M,N] = A[M,K] * Bt[N,K]^T + bias
// CTA tile 128x128, K-chunk 16, double-buffered cp.async.
// 8 warps, each 64x32 (4x4 m16n8k8 fragments).
// smem row stride 20 floats -> conflict-free fragment loads.
// ============================================================
#define TSTRIDE 20
#define TILE_FLOATS (128 * TSTRIDE)

__global__ __launch_bounds__(256) void tc_gemm(
    const float* __restrict__ A, const float* __restrict__ Bt,
    const float* __restrict__ bias, float* __restrict__ C,
    int M, int N, int K)
{
    __shared__ float As[2][TILE_FLOATS];
    __shared__ float Bs[2][TILE_FLOATS];

    const int tid  = threadIdx.x;
    const int warp = tid >> 5;
    const int lane = tid & 31;
    const int wm = warp >> 2;          // 0..1
    const int wn = warp & 3;           // 0..3
    const int m0 = blockIdx.y * 128;
    const int n0 = blockIdx.x * 128;

    const uint32_t aS = smem_u32(As);
    const uint32_t bS = smem_u32(Bs);

    // cp.async mapping: 512 16B-groups per tile, 2 per thread
    const int g0row = tid >> 2;        // rows 0..63 (i=0), 64..127 (i=1)
    const int g0c4  = (tid & 3) * 4;   // float offset 0,4,8,12

    float acc[4][4][4];
#pragma unroll
    for (int mt = 0; mt < 4; mt++)
#pragma unroll
        for (int nt = 0; nt < 4; nt++)
#pragma unroll
            for (int r = 0; r < 4; r++) acc[mt][nt][r] = 0.f;

    const int nch = K >> 4;

    // ---- load chunk helper (macro-ish lambda) ----
    auto load_chunk = [&](int st, int kc) {
#pragma unroll
        for (int i = 0; i < 2; i++) {
            int row = g0row + i * 64;
            uint32_t soff = (uint32_t)(row * TSTRIDE + g0c4) * 4;
            cpa16(aS + st * (TILE_FLOATS * 4) + soff,
                  A + (size_t)(m0 + row) * K + kc + g0c4);
            cpa16(bS + st * (TILE_FLOATS * 4) + soff,
                  Bt + (size_t)(n0 + row) * K + kc + g0c4);
        }
    };

    load_chunk(0, 0);
    CPA_COMMIT();

    for (int c = 0; c < nch; c++) {
        const int st = c & 1;
        if (c + 1 < nch) { load_chunk(st ^ 1, (c + 1) << 4); }
        CPA_COMMIT();
        if (c + 1 < nch) { CPA_WAIT1(); } else { CPA_WAIT0(); }
        __syncthreads();

        const float* Abase = &As[st][(wm * 64) * TSTRIDE];
        const float* Bbase = &Bs[st][(wn * 32) * TSTRIDE];
        const int r = lane >> 2, cq = lane & 3;

#pragma unroll
        for (int s = 0; s < 2; s++) {
            const int k8 = s * 8;
            uint32_t af[4][4];
#pragma unroll
            for (int mt = 0; mt < 4; mt++) {
                const float* ab = Abase + (mt * 16) * TSTRIDE + k8 + cq;
                af[mt][0] = __float_as_uint(ab[r * TSTRIDE]);
                af[mt][1] = __float_as_uint(ab[(r + 8) * TSTRIDE]);
                af[mt][2] = __float_as_uint(ab[r * TSTRIDE + 4]);
                af[mt][3] = __float_as_uint(ab[(r + 8) * TSTRIDE + 4]);
            }
            uint32_t bf[4][2];
#pragma unroll
            for (int nt = 0; nt < 4; nt++) {
                const float* bb = Bbase + (nt * 8 + r) * TSTRIDE + k8 + cq;
                bf[nt][0] = __float_as_uint(bb[0]);
                bf[nt][1] = __float_as_uint(bb[4]);
            }
#pragma unroll
            for (int mt = 0; mt < 4; mt++)
#pragma unroll
                for (int nt = 0; nt < 4; nt++)
                    mma1688(acc[mt][nt], af[mt], bf[nt]);
        }
        __syncthreads();
    }

    // epilogue: c0:(r, 2c) c1:(r, 2c+1) c2:(r+8, 2c) c3:(r+8, 2c+1)
    {
        const int r = lane >> 2, cq = lane & 3;
#pragma unroll
        for (int mt = 0; mt < 4; mt++) {
            int row = m0 + wm * 64 + mt * 16 + r;
#pragma unroll
            for (int nt = 0; nt < 4; nt++) {
                int col = n0 + wn * 32 + nt * 8 + 2 * cq;
                float2 bv = *(const float2*)(bias + col);
                float2 o0 = { acc[mt][nt][0] + bv.x, acc[mt][nt][1] + bv.y };
                float2 o1 = { acc[mt][nt][2] + bv.x, acc[mt][nt][3] + bv.y };
                *(float2*)(C + (size_t)row * N + col) = o0;
                *(float2*)(C + (size_t)(row + 8) * N + col) = o1;
            }
        }
    }
}

// ============================================================
// convert helpers
// ============================================================
__global__ void cvt_rna_kernel(const float* __restrict__ s, float* __restrict__ d, size_t n4)
{
    size_t i = (size_t)blockIdx.x * blockDim.x + threadIdx.x;
    if (i < n4) {
        float4 v = ((const float4*)s)[i];
        v.x = tf32r(v.x); v.y = tf32r(v.y); v.z = tf32r(v.z); v.w = tf32r(v.w);
        ((float4*)d)[i] = v;
    }
}

__global__ void cvtT_kernel(const float* __restrict__ src, float* __restrict__ dst,
                            int K, int N)
{
    __shared__ float tile[32][33];
    int k0 = blockIdx.y * 32, n0 = blockIdx.x * 32;
    int tx = threadIdx.x, ty = threadIdx.y;  // 32 x 8
#pragma unroll
    for (int i = 0; i < 32; i += 8)
        tile[ty + i][tx] = src[(size_t)(k0 + ty + i) * N + n0 + tx];
    __syncthreads();
#pragma unroll
    for (int i = 0; i < 32; i += 8)
        dst[(size_t)(n0 + ty + i) * K + k0 + tx] = tf32r(tile[tx][ty + i]);
}

// ============================================================
// RMSNorm + gain + RoPE
// ============================================================
__global__ __launch_bounds__(256) void rmsrope_kernel(
    const float* __restrict__ cosb, const float* __restrict__ sinb,
    const float* __restrict__ gq, const float* __restrict__ gk)
{
    const int t = blockIdx.x;
    const int tid = threadIdx.x;
    const float* base = g_qkv + (size_t)t * QKVDIM;

    float sq = 0.f, sk = 0.f;
    for (int i = tid; i < DIMM; i += 256) {
        float a = base[i];         sq = fmaf(a, a, sq);
        float b = base[DIMM + i];  sk = fmaf(b, b, sk);
    }
    __shared__ float r1[256], r2[256];
    r1[tid] = sq; r2[tid] = sk;
    __syncthreads();
    for (int s = 128; s > 0; s >>= 1) {
        if (tid < s) { r1[tid] += r1[tid + s]; r2[tid] += r2[tid + s]; }
        __syncthreads();
    }
    const float rq = rsqrtf(r1[0] / (float)DIMM + EPS);
    const float rk = rsqrtf(r2[0] / (float)DIMM + EPS);

    const int l = t & (LL - 1);
    const float* cl = cosb + (size_t)l * HDIM;
    const float* sl = sinb + (size_t)l * HDIM;
    float* qo = g_q + (size_t)t * DIMM;
    float* ko = g_k + (size_t)t * DIMM;

    for (int p = tid; p < DIMM / 2; p += 256) {
        int d = 2 * p;
        int hd = d & (HDIM - 1);
        float c = cl[hd];
        float s = sl[hd + 1];
        float x0 = base[d]     * rq * gq[d];
        float x1 = base[d + 1] * rq * gq[d + 1];
        qo[d]     = x0 * c - x1 * s;
        qo[d + 1] = x0 * s + x1 * c;
        float y0 = base[DIMM + d]     * rk * gk[d];
        float y1 = base[DIMM + d + 1] * rk * gk[d + 1];
        ko[d]     = y0 * c - y1 * s;
        ko[d + 1] = y0 * s + y1 * c;
    }
}

// ============================================================
// scores = SCALE * q k^T
// ============================================================
__global__ __launch_bounds__(256) void scores_kernel()
{
    const int bh = blockIdx.z;
    const int b = bh / NHEADS, h = bh % NHEADS;
    const float* qb = g_q + (size_t)b * LL * DIMM + h * HDIM;
    const float* kb = g_k + (size_t)b * LL * DIMM + h * HDIM;

    __shared__ float As[16][64];
    __shared__ float Bs[16][64];

    const int tid = threadIdx.x;
    const int tx = tid & 15, ty = tid >> 4;
    const int lrow = tid >> 2;
    const int lcol = (tid & 3) * 4;
    const int m0 = blockIdx.y * 64, n0 = blockIdx.x * 64;

    float acc[4][4];
#pragma unroll
    for (int i = 0; i < 4; i++)
#pragma unroll
        for (int j = 0; j < 4; j++) acc[i][j] = 0.f;

    for (int k0 = 0; k0 < HDIM; k0 += 16) {
        float4 av = *(const float4*)(qb + (size_t)(m0 + lrow) * DIMM + k0 + lcol);
        As[lcol + 0][lrow] = av.x; As[lcol + 1][lrow] = av.y;
        As[lcol + 2][lrow] = av.z; As[lcol + 3][lrow] = av.w;
        float4 bv = *(const float4*)(kb + (size_t)(n0 + lrow) * DIMM + k0 + lcol);
        Bs[lcol + 0][lrow] = bv.x; Bs[lcol + 1][lrow] = bv.y;
        Bs[lcol + 2][lrow] = bv.z; Bs[lcol + 3][lrow] = bv.w;
        __syncthreads();
#pragma unroll
        for (int kk = 0; kk < 16; kk++) {
            float a[4], bq[4];
            *(float4*)a  = *(const float4*)&As[kk][ty * 4];
            *(float4*)bq = *(const float4*)&Bs[kk][tx * 4];
#pragma unroll
            for (int i = 0; i < 4; i++)
#pragma unroll
                for (int j = 0; j < 4; j++)
                    acc[i][j] = fmaf(a[i], bq[j], acc[i][j]);
        }
        __syncthreads();
    }

    float* srow = g_scores + (size_t)bh * LL * LL;
#pragma unroll
    for (int i = 0; i < 4; i++)
#pragma unroll
        for (int j = 0; j < 4; j++)
            srow[(size_t)(m0 + ty * 4 + i) * LL + n0 + tx * 4 + j] = acc[i][j] * SCALE;
}

// ============================================================
// softmax
// ============================================================
__global__ __launch_bounds__(256) void softmax_kernel()
{
    __shared__ float red[256];
    float* row = g_scores + (size_t)blockIdx.x * LL;
    const int tid = threadIdx.x;

    float4 v = ((float4*)row)[tid];
    float m = fmaxf(fmaxf(v.x, v.y), fmaxf(v.z, v.w));
    red[tid] = m;
    __syncthreads();
    for (int s = 128; s > 0; s >>= 1) {
        if (tid < s) red[tid] = fmaxf(red[tid], red[tid + s]);
        __syncthreads();
    }
    m = red[0];
    __syncthreads();

    v.x = expf(v.x - m); v.y = expf(v.y - m);
    v.z = expf(v.z - m); v.w = expf(v.w - m);
    red[tid] = v.x + v.y + v.z + v.w;
    __syncthreads();
    for (int s = 128; s > 0; s >>= 1) {
        if (tid < s) red[tid] += red[tid + s];
        __syncthreads();
    }
    float inv = 1.f / red[0];
    v.x *= inv; v.y *= inv; v.z *= inv; v.w *= inv;
    ((float4*)row)[tid] = v;
}

// ============================================================
// o = P V (V read from g_qkv; output tf32-rounded for out-proj)
// ============================================================
__global__ __launch_bounds__(256) void pv_kernel()
{
    const int bh = blockIdx.z;
    const int b = bh / NHEADS, h = bh % NHEADS;
    const float* P = g_scores + (size_t)bh * LL * LL;
    const float* vb = g_qkv + (size_t)b * LL * QKVDIM + 2 * DIMM + h * HDIM;

    __shared__ float Ps[16][64];
    __shared__ float Vs[16][64];

    const int tid = threadIdx.x;
    const int tx = tid & 15, ty = tid >> 4;
    const int prow = tid >> 2;
    const int pcol = (tid & 3) * 4;
    const int vrow = tid >> 4;
    const int vcol = (tid & 15) * 4;
    const int m0 = blockIdx.y * 64, n0 = blockIdx.x * 64;

    float acc[4][4];
#pragma unroll
    for (int i = 0; i < 4; i++)
#pragma unroll
        for (int j = 0; j < 4; j++) acc[i][j] = 0.f;

    for (int k0 = 0; k0 < LL; k0 += 16) {
        float4 pv4 = *(const float4*)(P + (size_t)(m0 + prow) * LL + k0 + pcol);
        Ps[pcol + 0][prow] = pv4.x; Ps[pcol + 1][prow] = pv4.y;
        Ps[pcol + 2][prow] = pv4.z; Ps[pcol + 3][prow] = pv4.w;
        float4 vv = *(const float4*)(vb + (size_t)(k0 + vrow) * QKVDIM + n0 + vcol);
        *(float4*)&Vs[vrow][vcol] = vv;
        __syncthreads();
#pragma unroll
        for (int kk = 0; kk < 16; kk++) {
            float a[4], bq[4];
            *(float4*)a  = *(const float4*)&Ps[kk][ty * 4];
            *(float4*)bq = *(const float4*)&Vs[kk][tx * 4];
#pragma unroll
            for (int i = 0; i < 4; i++)
#pragma unroll
                for (int j = 0; j < 4; j++)
                    acc[i][j] = fmaf(a[i], bq[j], acc[i][j]);
        }
        __syncthreads();
    }

#pragma unroll
    for (int i = 0; i < 4; i++)
#pragma unroll
        for (int j = 0; j < 4; j++)
            g_o[(size_t)(b * LL + m0 + ty * 4 + i) * DIMM + h * HDIM + n0 + tx * 4 + j]
                = tf32r(acc[i][j]);
}

// ============================================================
// launch
// ============================================================
extern "C" void kernel_launch(void* const* d_in, const int* in_sizes, int n_in,
                              void* d_out, int out_size)
{
    const float* x     = (const float*)d_in[0];
    const float* cosb  = (const float*)d_in[1];
    const float* sinb  = (const float*)d_in[2];
    const float* Wqkv  = (const float*)d_in[3];
    const float* bqkv  = (const float*)d_in[4];
    const float* gq    = (const float*)d_in[5];
    const float* gk    = (const float*)d_in[6];
    const float* Wout  = (const float*)d_in[7];
    const float* bout  = (const float*)d_in[8];
    float* out = (float*)d_out;

    void* p_qkv; cudaGetSymbolAddress(&p_qkv, g_qkv);
    void* p_o;   cudaGetSymbolAddress(&p_o,   g_o);
    void* p_wq;  cudaGetSymbolAddress(&p_wq,  g_wq);
    void* p_wo;  cudaGetSymbolAddress(&p_wo,  g_wo);
    void* p_x;   cudaGetSymbolAddress(&p_x,   g_x);

    // 0) weight transpose + tf32 rounding; activation rounding
    cvtT_kernel<<<dim3(QKVDIM / 32, DIMM / 32), dim3(32, 8)>>>(Wqkv, (float*)p_wq, DIMM, QKVDIM);
    cvtT_kernel<<<dim3(DIMM / 32,  DIMM / 32), dim3(32, 8)>>>(Wout, (float*)p_wo, DIMM, DIMM);
    {
        size_t n4 = (size_t)TOKENS * DIMM / 4;
        cvt_rna_kernel<<<(unsigned)((n4 + 255) / 256), 256>>>(x, (float*)p_x, n4);
    }

    // 1) QKV projection (tensor cores, tf32)
    tc_gemm<<<dim3(QKVDIM / 128, TOKENS / 128), 256>>>(
        (const float*)p_x, (const float*)p_wq, bqkv, (float*)p_qkv,
        TOKENS, QKVDIM, DIMM);

    // 2) RMSNorm + RoPE
    rmsrope_kernel<<<TOKENS, 256>>>(cosb, sinb, gq, gk);

    // 3) scores
    scores_kernel<<<dim3(LL / 64, LL / 64, BB * NHEADS), 256>>>();

    // 4) softmax
    softmax_kernel<<<BB * NHEADS * LL, 256>>>();

    // 5) o = P V
    pv_kernel<<<dim3(HDIM / 64, LL / 64, BB * NHEADS), 256>>>();

    // 6) out projection (tensor cores, tf32)
    tc_gemm<<<dim3(DIMM / 128, TOKENS / 128), 256>>>(
        (const float*)p_o, (const float*)p_wo, bout, out,
        TOKENS, DIMM, DIMM);
}

// round 4
// speedup vs baseline: 3.7839x; 2.1336x over previous
#include <cuda_runtime.h>
#include <cuda_bf16.h>
#include <math.h>
#include <stdint.h>

// Problem constants
#define DIMM 5120
#define NHEADS 40
#define HDIM 128
#define BB 2
#define LL 1024
#define TOKENS (BB*LL)          // 2048
#define QKVDIM (3*DIMM)         // 15360
#define SCALE 0.08838834764831845f
#define EPS 1e-6f

// -------- scratch (static device globals; no runtime allocation) --------
__device__ float g_qkv[(size_t)TOKENS * QKVDIM];          // 125.8 MB
__device__ float g_q[(size_t)TOKENS * DIMM];
__device__ float g_k[(size_t)TOKENS * DIMM];
__device__ float g_scores[(size_t)BB * NHEADS * LL * LL]; // 335.5 MB
__device__ float g_o[(size_t)TOKENS * DIMM];
__device__ float g_vt[(size_t)BB * NHEADS * HDIM * LL];   // V^T per head, tf32
__device__ float g_wq[(size_t)QKVDIM * DIMM];             // W_qkv^T tf32 [N,K]
__device__ float g_wo[(size_t)DIMM * DIMM];               // W_out^T tf32 [N,K]
__device__ float g_x[(size_t)TOKENS * DIMM];              // x tf32-rounded

// ============================================================
// helpers
// ============================================================
__device__ __forceinline__ uint32_t smem_u32(const void* p) {
    uint32_t a;
    asm("{ .reg .u64 t; cvta.to.shared.u64 t, %1; cvt.u32.u64 %0, t; }" : "=r"(a) : "l"(p));
    return a;
}
__device__ __forceinline__ float tf32r(float x) {
    float y; asm("cvt.rna.tf32.f32 %0, %1;" : "=f"(y) : "f"(x)); return y;
}
__device__ __forceinline__ void cpa16(uint32_t dst, const void* src) {
    asm volatile("cp.async.cg.shared.global [%0], [%1], 16;" :: "r"(dst), "l"(src));
}
#define CPA_COMMIT() asm volatile("cp.async.commit_group;" ::: "memory")
#define CPA_WAIT1()  asm volatile("cp.async.wait_group 1;" ::: "memory")
#define CPA_WAIT0()  asm volatile("cp.async.wait_group 0;" ::: "memory")

__device__ __forceinline__ void mma1688(float* d, const uint32_t* a, const uint32_t* b) {
    asm volatile(
        "mma.sync.aligned.m16n8k8.row.col.f32.tf32.tf32.f32 "
        "{%0,%1,%2,%3}, {%4,%5,%6,%7}, {%8,%9}, {%0,%1,%2,%3};"
        : "+f"(d[0]), "+f"(d[1]), "+f"(d[2]), "+f"(d[3])
        : "r"(a[0]), "r"(a[1]), "r"(a[2]), "r"(a[3]), "r"(b[0]), "r"(b[1]));
}

// ============================================================
// Generalized tf32 mma.sync GEMM:
//   C[z][m,n] = alpha * A[z][m,:K] * Bt[z][n,:K]^T (+ bias[n])
// CTA tile 128x128, K-chunk 32, double-buffered cp.async (dynamic smem).
// 8 warps, each 64x32 (4x4 m16n8k8 frags).
// smem rows stride 36 floats: fragment LDS bank = (4r+cq+k8)%32 -> conflict-free.
// ============================================================
#define KC2 32
#define TST 36
#define TILE_F (128 * TST)                 // 4608 floats per tile
#define STAGE_F (2 * TILE_F)               // A tile + B tile
#define GEMM_SMEM (2 * STAGE_F * 4)        // 73728 bytes

__global__ __launch_bounds__(256) void tc_gemm(
    const float* __restrict__ A, const float* __restrict__ Bt,
    const float* __restrict__ bias, float* __restrict__ C,
    long sAz, long sBz, long sCz,
    int lda, int ldb, int ldc, int K, float alpha, int round_out)
{
    extern __shared__ float sm[];
    const uint32_t sb = smem_u32(sm);

    A  += (size_t)blockIdx.z * sAz;
    Bt += (size_t)blockIdx.z * sBz;
    C  += (size_t)blockIdx.z * sCz;

    const int tid  = threadIdx.x;
    const int warp = tid >> 5;
    const int lane = tid & 31;
    const int wm = warp >> 2;          // 0..1
    const int wn = warp & 3;           // 0..3
    const int m0 = blockIdx.y * 128;
    const int n0 = blockIdx.x * 128;

    // cp.async mapping: 1024 16B-granules per tile, 4 per thread
    const int grow = tid >> 3;         // +32*i
    const int gc4  = (tid & 7) * 4;    // 0..28

    float acc[4][4][4];
#pragma unroll
    for (int mt = 0; mt < 4; mt++)
#pragma unroll
        for (int nt = 0; nt < 4; nt++)
#pragma unroll
            for (int r = 0; r < 4; r++) acc[mt][nt][r] = 0.f;

    const int nch = K / KC2;

    auto load_chunk = [&](int st, int kc) {
        uint32_t base = sb + (uint32_t)st * (STAGE_F * 4);
#pragma unroll
        for (int i = 0; i < 4; i++) {
            int row = grow + i * 32;
            uint32_t off = (uint32_t)(row * TST + gc4) * 4;
            cpa16(base + off,                A + (size_t)(m0 + row) * lda + kc + gc4);
            cpa16(base + TILE_F * 4 + off,   Bt + (size_t)(n0 + row) * ldb + kc + gc4);
        }
    };

    load_chunk(0, 0);
    CPA_COMMIT();

    for (int c = 0; c < nch; c++) {
        const int st = c & 1;
        if (c + 1 < nch) load_chunk(st ^ 1, (c + 1) * KC2);
        CPA_COMMIT();
        if (c + 1 < nch) { CPA_WAIT1(); } else { CPA_WAIT0(); }
        __syncthreads();

        const float* Abase = sm + st * STAGE_F + (wm * 64) * TST;
        const float* Bbase = sm + st * STAGE_F + TILE_F + (wn * 32) * TST;
        const int r = lane >> 2, cq = lane & 3;

#pragma unroll
        for (int s = 0; s < 4; s++) {
            const int k8 = s * 8;
            uint32_t af[4][4];
#pragma unroll
            for (int mt = 0; mt < 4; mt++) {
                const float* ab = Abase + (mt * 16) * TST + k8 + cq;
                af[mt][0] = __float_as_uint(ab[r * TST]);
                af[mt][1] = __float_as_uint(ab[(r + 8) * TST]);
                af[mt][2] = __float_as_uint(ab[r * TST + 4]);
                af[mt][3] = __float_as_uint(ab[(r + 8) * TST + 4]);
            }
            uint32_t bf[4][2];
#pragma unroll
            for (int nt = 0; nt < 4; nt++) {
                const float* bb = Bbase + (nt * 8 + r) * TST + k8 + cq;
                bf[nt][0] = __float_as_uint(bb[0]);
                bf[nt][1] = __float_as_uint(bb[4]);
            }
#pragma unroll
            for (int mt = 0; mt < 4; mt++)
#pragma unroll
                for (int nt = 0; nt < 4; nt++)
                    mma1688(acc[mt][nt], af[mt], bf[nt]);
        }
        __syncthreads();
    }

    // epilogue
    {
        const int r = lane >> 2, cq = lane & 3;
#pragma unroll
        for (int mt = 0; mt < 4; mt++) {
            int row = m0 + wm * 64 + mt * 16 + r;
#pragma unroll
            for (int nt = 0; nt < 4; nt++) {
                int col = n0 + wn * 32 + nt * 8 + 2 * cq;
                float2 bv = make_float2(0.f, 0.f);
                if (bias) bv = *(const float2*)(bias + col);
                float o0x = fmaf(acc[mt][nt][0], alpha, bv.x);
                float o0y = fmaf(acc[mt][nt][1], alpha, bv.y);
                float o1x = fmaf(acc[mt][nt][2], alpha, bv.x);
                float o1y = fmaf(acc[mt][nt][3], alpha, bv.y);
                if (round_out) { o0x = tf32r(o0x); o0y = tf32r(o0y);
                                 o1x = tf32r(o1x); o1y = tf32r(o1y); }
                *(float2*)(C + (size_t)row * ldc + col) = make_float2(o0x, o0y);
                *(float2*)(C + (size_t)(row + 8) * ldc + col) = make_float2(o1x, o1y);
            }
        }
    }
}

// ============================================================
// convert helpers
// ============================================================
__global__ void cvt_rna_kernel(const float* __restrict__ s, float* __restrict__ d, size_t n4)
{
    size_t i = (size_t)blockIdx.x * blockDim.x + threadIdx.x;
    if (i < n4) {
        float4 v = ((const float4*)s)[i];
        v.x = tf32r(v.x); v.y = tf32r(v.y); v.z = tf32r(v.z); v.w = tf32r(v.w);
        ((float4*)d)[i] = v;
    }
}

__global__ void cvtT_kernel(const float* __restrict__ src, float* __restrict__ dst,
                            int K, int N)
{
    __shared__ float tile[32][33];
    int k0 = blockIdx.y * 32, n0 = blockIdx.x * 32;
    int tx = threadIdx.x, ty = threadIdx.y;  // 32 x 8
#pragma unroll
    for (int i = 0; i < 32; i += 8)
        tile[ty + i][tx] = src[(size_t)(k0 + ty + i) * N + n0 + tx];
    __syncthreads();
#pragma unroll
    for (int i = 0; i < 32; i += 8)
        dst[(size_t)(n0 + ty + i) * K + k0 + tx] = tf32r(tile[tx][ty + i]);
}

// V^T per head: g_vt[bh][d][k] = tf32r(v[b,k,h,d]). grid (32,4,80), block (32,8)
__global__ void vtrans_kernel()
{
    __shared__ float tile[32][33];
    const int bh = blockIdx.z;
    const int b = bh / NHEADS, h = bh % NHEADS;
    const int k0 = blockIdx.x * 32, d0 = blockIdx.y * 32;
    const float* src = g_qkv + (size_t)b * LL * QKVDIM + 2 * DIMM + h * HDIM;
    float* dst = g_vt + (size_t)bh * HDIM * LL;
    int tx = threadIdx.x, ty = threadIdx.y;
#pragma unroll
    for (int i = 0; i < 32; i += 8)
        tile[ty + i][tx] = src[(size_t)(k0 + ty + i) * QKVDIM + d0 + tx];
    __syncthreads();
#pragma unroll
    for (int i = 0; i < 32; i += 8)
        dst[(size_t)(d0 + ty + i) * LL + k0 + tx] = tf32r(tile[tx][ty + i]);
}

// ============================================================
// RMSNorm + gain + RoPE -> tf32-rounded q,k
// ============================================================
__global__ __launch_bounds__(256) void rmsrope_kernel(
    const float* __restrict__ cosb, const float* __restrict__ sinb,
    const float* __restrict__ gq, const float* __restrict__ gk)
{
    const int t = blockIdx.x;
    const int tid = threadIdx.x;
    const float* base = g_qkv + (size_t)t * QKVDIM;

    float sq = 0.f, sk = 0.f;
    for (int i = tid; i < DIMM; i += 256) {
        float a = base[i];         sq = fmaf(a, a, sq);
        float b = base[DIMM + i];  sk = fmaf(b, b, sk);
    }
    __shared__ float r1[256], r2[256];
    r1[tid] = sq; r2[tid] = sk;
    __syncthreads();
    for (int s = 128; s > 0; s >>= 1) {
        if (tid < s) { r1[tid] += r1[tid + s]; r2[tid] += r2[tid + s]; }
        __syncthreads();
    }
    const float rq = rsqrtf(r1[0] / (float)DIMM + EPS);
    const float rk = rsqrtf(r2[0] / (float)DIMM + EPS);

    const int l = t & (LL - 1);
    const float* cl = cosb + (size_t)l * HDIM;
    const float* sl = sinb + (size_t)l * HDIM;
    float* qo = g_q + (size_t)t * DIMM;
    float* ko = g_k + (size_t)t * DIMM;

    for (int p = tid; p < DIMM / 2; p += 256) {
        int d = 2 * p;
        int hd = d & (HDIM - 1);
        float c = cl[hd];
        float s = sl[hd + 1];
        float x0 = base[d]     * rq * gq[d];
        float x1 = base[d + 1] * rq * gq[d + 1];
        qo[d]     = tf32r(x0 * c - x1 * s);
        qo[d + 1] = tf32r(x0 * s + x1 * c);
        float y0 = base[DIMM + d]     * rk * gk[d];
        float y1 = base[DIMM + d + 1] * rk * gk[d + 1];
        ko[d]     = tf32r(y0 * c - y1 * s);
        ko[d + 1] = tf32r(y0 * s + y1 * c);
    }
}

// ============================================================
// softmax over last dim (1024); stores tf32-rounded probs
// ============================================================
__global__ __launch_bounds__(256) void softmax_kernel()
{
    __shared__ float red[256];
    float* row = g_scores + (size_t)blockIdx.x * LL;
    const int tid = threadIdx.x;

    float4 v = ((float4*)row)[tid];
    float m = fmaxf(fmaxf(v.x, v.y), fmaxf(v.z, v.w));
    red[tid] = m;
    __syncthreads();
    for (int s = 128; s > 0; s >>= 1) {
        if (tid < s) red[tid] = fmaxf(red[tid], red[tid + s]);
        __syncthreads();
    }
    m = red[0];
    __syncthreads();

    v.x = expf(v.x - m); v.y = expf(v.y - m);
    v.z = expf(v.z - m); v.w = expf(v.w - m);
    red[tid] = v.x + v.y + v.z + v.w;
    __syncthreads();
    for (int s = 128; s > 0; s >>= 1) {
        if (tid < s) red[tid] += red[tid + s];
        __syncthreads();
    }
    float inv = 1.f / red[0];
    v.x = tf32r(v.x * inv); v.y = tf32r(v.y * inv);
    v.z = tf32r(v.z * inv); v.w = tf32r(v.w * inv);
    ((float4*)row)[tid] = v;
}

// ============================================================
// launch
// ============================================================
extern "C" void kernel_launch(void* const* d_in, const int* in_sizes, int n_in,
                              void* d_out, int out_size)
{
    const float* x     = (const float*)d_in[0];
    const float* cosb  = (const float*)d_in[1];
    const float* sinb  = (const float*)d_in[2];
    const float* Wqkv  = (const float*)d_in[3];
    const float* bqkv  = (const float*)d_in[4];
    const float* gq    = (const float*)d_in[5];
    const float* gk    = (const float*)d_in[6];
    const float* Wout  = (const float*)d_in[7];
    const float* bout  = (const float*)d_in[8];
    float* out = (float*)d_out;

    void* p_qkv; cudaGetSymbolAddress(&p_qkv, g_qkv);
    void* p_o;   cudaGetSymbolAddress(&p_o,   g_o);
    void* p_q;   cudaGetSymbolAddress(&p_q,   g_q);
    void* p_k;   cudaGetSymbolAddress(&p_k,   g_k);
    void* p_s;   cudaGetSymbolAddress(&p_s,   g_scores);
    void* p_vt;  cudaGetSymbolAddress(&p_vt,  g_vt);
    void* p_wq;  cudaGetSymbolAddress(&p_wq,  g_wq);
    void* p_wo;  cudaGetSymbolAddress(&p_wo,  g_wo);
    void* p_x;   cudaGetSymbolAddress(&p_x,   g_x);

    static int smem_set = 0;
    if (!smem_set) {
        cudaFuncSetAttribute(tc_gemm, cudaFuncAttributeMaxDynamicSharedMemorySize, GEMM_SMEM);
        smem_set = 1;
    }

    // 0) weight transpose + tf32 rounding; activation rounding
    cvtT_kernel<<<dim3(QKVDIM / 32, DIMM / 32), dim3(32, 8)>>>(Wqkv, (float*)p_wq, DIMM, QKVDIM);
    cvtT_kernel<<<dim3(DIMM / 32,  DIMM / 32), dim3(32, 8)>>>(Wout, (float*)p_wo, DIMM, DIMM);
    {
        size_t n4 = (size_t)TOKENS * DIMM / 4;
        cvt_rna_kernel<<<(unsigned)((n4 + 255) / 256), 256>>>(x, (float*)p_x, n4);
    }

    // 1) QKV projection
    tc_gemm<<<dim3(QKVDIM / 128, TOKENS / 128, 1), 256, GEMM_SMEM>>>(
        (const float*)p_x, (const float*)p_wq, bqkv, (float*)p_qkv,
        0, 0, 0, DIMM, DIMM, QKVDIM, DIMM, 1.f, 0);

    // 2) RMSNorm + RoPE (tf32 out), V transpose (tf32 out)
    rmsrope_kernel<<<TOKENS, 256>>>(cosb, sinb, gq, gk);
    vtrans_kernel<<<dim3(LL / 32, HDIM / 32, BB * NHEADS), dim3(32, 8)>>>();

    // 3) scores = SCALE * q k^T  (tensor cores; z = head, per batch)
    for (int b = 0; b < BB; b++) {
        tc_gemm<<<dim3(LL / 128, LL / 128, NHEADS), 256, GEMM_SMEM>>>(
            (const float*)p_q + (size_t)b * LL * DIMM,
            (const float*)p_k + (size_t)b * LL * DIMM,
            nullptr,
            (float*)p_s + (size_t)b * NHEADS * LL * LL,
            HDIM, HDIM, (long)LL * LL,
            DIMM, DIMM, LL, HDIM, SCALE, 0);
    }

    // 4) softmax (tf32-rounded probs)
    softmax_kernel<<<BB * NHEADS * LL, 256>>>();

    // 5) o = P V  (tensor cores; z = head, per batch); tf32-rounded out
    for (int b = 0; b < BB; b++) {
        tc_gemm<<<dim3(HDIM / 128, LL / 128, NHEADS), 256, GEMM_SMEM>>>(
            (const float*)p_s + (size_t)b * NHEADS * LL * LL,
            (const float*)p_vt + (size_t)b * NHEADS * HDIM * LL,
            nullptr,
            (float*)p_o + (size_t)b * LL * DIMM,
            (long)LL * LL, (long)HDIM * LL, HDIM,
            LL, LL, DIMM, LL, 1.f, 1);
    }

    // 6) out projection
    tc_gemm<<<dim3(DIMM / 128, TOKENS / 128, 1), 256, GEMM_SMEM>>>(
        (const float*)p_o, (const float*)p_wo, bout, out,
        0, 0, 0, DIMM, DIMM, DIMM, DIMM, 1.f, 0);
}

// round 5
// speedup vs baseline: 4.0568x; 1.0721x over previous
#include <cuda_runtime.h>
#include <cuda_bf16.h>
#include <math.h>
#include <stdint.h>

// Problem constants
#define DIMM 5120
#define NHEADS 40
#define HDIM 128
#define BB 2
#define LL 1024
#define TOKENS (BB*LL)          // 2048
#define QKVDIM (3*DIMM)         // 15360
#define SCALE 0.08838834764831845f
#define EPS 1e-6f

// -------- scratch (static device globals; no runtime allocation) --------
__device__ float g_qkv[(size_t)TOKENS * QKVDIM];          // 125.8 MB
__device__ float g_q[(size_t)TOKENS * DIMM];
__device__ float g_k[(size_t)TOKENS * DIMM];
__device__ float g_scores[(size_t)BB * NHEADS * LL * LL]; // 335.5 MB
__device__ float g_o[(size_t)TOKENS * DIMM];
__device__ float g_vt[(size_t)BB * NHEADS * HDIM * LL];   // V^T per head, tf32
__device__ float g_wq[(size_t)QKVDIM * DIMM];             // W_qkv^T tf32 [N,K]
__device__ float g_wo[(size_t)DIMM * DIMM];               // W_out^T tf32 [N,K]
__device__ float g_x[(size_t)TOKENS * DIMM];              // x tf32-rounded

// ============================================================
// helpers
// ============================================================
__device__ __forceinline__ uint32_t smem_u32(const void* p) {
    uint32_t a;
    asm("{ .reg .u64 t; cvta.to.shared.u64 t, %1; cvt.u32.u64 %0, t; }" : "=r"(a) : "l"(p));
    return a;
}
__device__ __forceinline__ float tf32r(float x) {
    float y; asm("cvt.rna.tf32.f32 %0, %1;" : "=f"(y) : "f"(x)); return y;
}
__device__ __forceinline__ void cpa16(uint32_t dst, const void* src) {
    asm volatile("cp.async.cg.shared.global [%0], [%1], 16;" :: "r"(dst), "l"(src));
}
#define CPA_COMMIT() asm volatile("cp.async.commit_group;" ::: "memory")
#define CPA_WAIT1()  asm volatile("cp.async.wait_group 1;" ::: "memory")
#define CPA_WAIT0()  asm volatile("cp.async.wait_group 0;" ::: "memory")

__device__ __forceinline__ void mma1688(float* d, const uint32_t* a, const uint32_t* b) {
    asm volatile(
        "mma.sync.aligned.m16n8k8.row.col.f32.tf32.tf32.f32 "
        "{%0,%1,%2,%3}, {%4,%5,%6,%7}, {%8,%9}, {%0,%1,%2,%3};"
        : "+f"(d[0]), "+f"(d[1]), "+f"(d[2]), "+f"(d[3])
        : "r"(a[0]), "r"(a[1]), "r"(a[2]), "r"(a[3]), "r"(b[0]), "r"(b[1]));
}

// ============================================================
// Generalized tf32 mma.sync GEMM:
//   C[z][m,n] = alpha * A[z][m,:K] * Bt[z][n,:K]^T (+ bias[n])
// CTA tile 128x128, K-chunk 32, THREE-stage cp.async pipeline,
// single __syncthreads per chunk, loads issued right after barrier.
// Grid: blockIdx.x = M tile, blockIdx.y = N tile (L2-friendly waves).
// 8 warps, each 64x32 (4x4 m16n8k8 frags).
// smem rows stride 36 floats -> conflict-free fragment LDS.
// ============================================================
#define KC2 32
#define TST 36
#define TILE_F (128 * TST)                 // 4608 floats per tile
#define STAGE_F (2 * TILE_F)               // A tile + B tile
#define NSTG 3
#define GEMM_SMEM (NSTG * STAGE_F * 4)     // 110592 bytes

__global__ __launch_bounds__(256) void tc_gemm(
    const float* __restrict__ A, const float* __restrict__ Bt,
    const float* __restrict__ bias, float* __restrict__ C,
    long sAz, long sBz, long sCz,
    int lda, int ldb, int ldc, int K, float alpha, int round_out)
{
    extern __shared__ float sm[];
    const uint32_t sb = smem_u32(sm);

    A  += (size_t)blockIdx.z * sAz;
    Bt += (size_t)blockIdx.z * sBz;
    C  += (size_t)blockIdx.z * sCz;

    const int tid  = threadIdx.x;
    const int warp = tid >> 5;
    const int lane = tid & 31;
    const int wm = warp >> 2;          // 0..1
    const int wn = warp & 3;           // 0..3
    const int m0 = blockIdx.x * 128;   // M on x (wave covers all M quickly)
    const int n0 = blockIdx.y * 128;

    // cp.async mapping: 1024 16B-granules per tile, 4 per thread
    const int grow = tid >> 3;         // +32*i
    const int gc4  = (tid & 7) * 4;    // 0..28

    float acc[4][4][4];
#pragma unroll
    for (int mt = 0; mt < 4; mt++)
#pragma unroll
        for (int nt = 0; nt < 4; nt++)
#pragma unroll
            for (int r = 0; r < 4; r++) acc[mt][nt][r] = 0.f;

    const int nch = K / KC2;

    auto load_chunk = [&](int st, int kc) {
        uint32_t base = sb + (uint32_t)st * (STAGE_F * 4);
#pragma unroll
        for (int i = 0; i < 4; i++) {
            int row = grow + i * 32;
            uint32_t off = (uint32_t)(row * TST + gc4) * 4;
            cpa16(base + off,                A + (size_t)(m0 + row) * lda + kc + gc4);
            cpa16(base + TILE_F * 4 + off,   Bt + (size_t)(n0 + row) * ldb + kc + gc4);
        }
    };

    load_chunk(0, 0);       CPA_COMMIT();
    if (nch > 1) { load_chunk(1, KC2); CPA_COMMIT(); }

    const int r = lane >> 2, cq = lane & 3;

    for (int c = 0; c < nch; c++) {
        const int st = c % NSTG;
        if (c + 1 < nch) { CPA_WAIT1(); } else { CPA_WAIT0(); }
        __syncthreads();
        // stage (c+2)%3 == (c-1)%3 is free: barrier above followed everyone's compute(c-1)
        if (c + 2 < nch) { load_chunk((c + 2) % NSTG, (c + 2) * KC2); CPA_COMMIT(); }

        const float* Abase = sm + st * STAGE_F + (wm * 64) * TST;
        const float* Bbase = sm + st * STAGE_F + TILE_F + (wn * 32) * TST;

#pragma unroll
        for (int s = 0; s < 4; s++) {
            const int k8 = s * 8;
            uint32_t af[4][4];
#pragma unroll
            for (int mt = 0; mt < 4; mt++) {
                const float* ab = Abase + (mt * 16) * TST + k8 + cq;
                af[mt][0] = __float_as_uint(ab[r * TST]);
                af[mt][1] = __float_as_uint(ab[(r + 8) * TST]);
                af[mt][2] = __float_as_uint(ab[r * TST + 4]);
                af[mt][3] = __float_as_uint(ab[(r + 8) * TST + 4]);
            }
            uint32_t bf[4][2];
#pragma unroll
            for (int nt = 0; nt < 4; nt++) {
                const float* bb = Bbase + (nt * 8 + r) * TST + k8 + cq;
                bf[nt][0] = __float_as_uint(bb[0]);
                bf[nt][1] = __float_as_uint(bb[4]);
            }
#pragma unroll
            for (int mt = 0; mt < 4; mt++)
#pragma unroll
                for (int nt = 0; nt < 4; nt++)
                    mma1688(acc[mt][nt], af[mt], bf[nt]);
        }
    }

    // epilogue
    {
#pragma unroll
        for (int mt = 0; mt < 4; mt++) {
            int row = m0 + wm * 64 + mt * 16 + r;
#pragma unroll
            for (int nt = 0; nt < 4; nt++) {
                int col = n0 + wn * 32 + nt * 8 + 2 * cq;
                float2 bv = make_float2(0.f, 0.f);
                if (bias) bv = *(const float2*)(bias + col);
                float o0x = fmaf(acc[mt][nt][0], alpha, bv.x);
                float o0y = fmaf(acc[mt][nt][1], alpha, bv.y);
                float o1x = fmaf(acc[mt][nt][2], alpha, bv.x);
                float o1y = fmaf(acc[mt][nt][3], alpha, bv.y);
                if (round_out) { o0x = tf32r(o0x); o0y = tf32r(o0y);
                                 o1x = tf32r(o1x); o1y = tf32r(o1y); }
                *(float2*)(C + (size_t)row * ldc + col) = make_float2(o0x, o0y);
                *(float2*)(C + (size_t)(row + 8) * ldc + col) = make_float2(o1x, o1y);
            }
        }
    }
}

// ============================================================
// convert helpers
// ============================================================
__global__ void cvt_rna_kernel(const float* __restrict__ s, float* __restrict__ d, size_t n4)
{
    size_t i = (size_t)blockIdx.x * blockDim.x + threadIdx.x;
    if (i < n4) {
        float4 v = ((const float4*)s)[i];
        v.x = tf32r(v.x); v.y = tf32r(v.y); v.z = tf32r(v.z); v.w = tf32r(v.w);
        ((float4*)d)[i] = v;
    }
}

__global__ void cvtT_kernel(const float* __restrict__ src, float* __restrict__ dst,
                            int K, int N)
{
    __shared__ float tile[32][33];
    int k0 = blockIdx.y * 32, n0 = blockIdx.x * 32;
    int tx = threadIdx.x, ty = threadIdx.y;  // 32 x 8
#pragma unroll
    for (int i = 0; i < 32; i += 8)
        tile[ty + i][tx] = src[(size_t)(k0 + ty + i) * N + n0 + tx];
    __syncthreads();
#pragma unroll
    for (int i = 0; i < 32; i += 8)
        dst[(size_t)(n0 + ty + i) * K + k0 + tx] = tf32r(tile[tx][ty + i]);
}

// V^T per head: g_vt[bh][d][k] = tf32r(v[b,k,h,d]). grid (32,4,80), block (32,8)
__global__ void vtrans_kernel()
{
    __shared__ float tile[32][33];
    const int bh = blockIdx.z;
    const int b = bh / NHEADS, h = bh % NHEADS;
    const int k0 = blockIdx.x * 32, d0 = blockIdx.y * 32;
    const float* src = g_qkv + (size_t)b * LL * QKVDIM + 2 * DIMM + h * HDIM;
    float* dst = g_vt + (size_t)bh * HDIM * LL;
    int tx = threadIdx.x, ty = threadIdx.y;
#pragma unroll
    for (int i = 0; i < 32; i += 8)
        tile[ty + i][tx] = src[(size_t)(k0 + ty + i) * QKVDIM + d0 + tx];
    __syncthreads();
#pragma unroll
    for (int i = 0; i < 32; i += 8)
        dst[(size_t)(d0 + ty + i) * LL + k0 + tx] = tf32r(tile[tx][ty + i]);
}

// ============================================================
// RMSNorm + gain + RoPE -> tf32-rounded q,k
// ============================================================
__global__ __launch_bounds__(256) void rmsrope_kernel(
    const float* __restrict__ cosb, const float* __restrict__ sinb,
    const float* __restrict__ gq, const float* __restrict__ gk)
{
    const int t = blockIdx.x;
    const int tid = threadIdx.x;
    const float* base = g_qkv + (size_t)t * QKVDIM;

    float sq = 0.f, sk = 0.f;
    for (int i = tid; i < DIMM; i += 256) {
        float a = base[i];         sq = fmaf(a, a, sq);
        float b = base[DIMM + i];  sk = fmaf(b, b, sk);
    }
    __shared__ float r1[256], r2[256];
    r1[tid] = sq; r2[tid] = sk;
    __syncthreads();
    for (int s = 128; s > 0; s >>= 1) {
        if (tid < s) { r1[tid] += r1[tid + s]; r2[tid] += r2[tid + s]; }
        __syncthreads();
    }
    const float rq = rsqrtf(r1[0] / (float)DIMM + EPS);
    const float rk = rsqrtf(r2[0] / (float)DIMM + EPS);

    const int l = t & (LL - 1);
    const float* cl = cosb + (size_t)l * HDIM;
    const float* sl = sinb + (size_t)l * HDIM;
    float* qo = g_q + (size_t)t * DIMM;
    float* ko = g_k + (size_t)t * DIMM;

    for (int p = tid; p < DIMM / 2; p += 256) {
        int d = 2 * p;
        int hd = d & (HDIM - 1);
        float c = cl[hd];
        float s = sl[hd + 1];
        float x0 = base[d]     * rq * gq[d];
        float x1 = base[d + 1] * rq * gq[d + 1];
        qo[d]     = tf32r(x0 * c - x1 * s);
        qo[d + 1] = tf32r(x0 * s + x1 * c);
        float y0 = base[DIMM + d]     * rk * gk[d];
        float y1 = base[DIMM + d + 1] * rk * gk[d + 1];
        ko[d]     = tf32r(y0 * c - y1 * s);
        ko[d + 1] = tf32r(y0 * s + y1 * c);
    }
}

// ============================================================
// softmax over last dim (1024); stores tf32-rounded probs
// ============================================================
__global__ __launch_bounds__(256) void softmax_kernel()
{
    __shared__ float red[256];
    float* row = g_scores + (size_t)blockIdx.x * LL;
    const int tid = threadIdx.x;

    float4 v = ((float4*)row)[tid];
    float m = fmaxf(fmaxf(v.x, v.y), fmaxf(v.z, v.w));
    red[tid] = m;
    __syncthreads();
    for (int s = 128; s > 0; s >>= 1) {
        if (tid < s) red[tid] = fmaxf(red[tid], red[tid + s]);
        __syncthreads();
    }
    m = red[0];
    __syncthreads();

    v.x = expf(v.x - m); v.y = expf(v.y - m);
    v.z = expf(v.z - m); v.w = expf(v.w - m);
    red[tid] = v.x + v.y + v.z + v.w;
    __syncthreads();
    for (int s = 128; s > 0; s >>= 1) {
        if (tid < s) red[tid] += red[tid + s];
        __syncthreads();
    }
    float inv = 1.f / red[0];
    v.x = tf32r(v.x * inv); v.y = tf32r(v.y * inv);
    v.z = tf32r(v.z * inv); v.w = tf32r(v.w * inv);
    ((float4*)row)[tid] = v;
}

// ============================================================
// launch
// ============================================================
extern "C" void kernel_launch(void* const* d_in, const int* in_sizes, int n_in,
                              void* d_out, int out_size)
{
    const float* x     = (const float*)d_in[0];
    const float* cosb  = (const float*)d_in[1];
    const float* sinb  = (const float*)d_in[2];
    const float* Wqkv  = (const float*)d_in[3];
    const float* bqkv  = (const float*)d_in[4];
    const float* gq    = (const float*)d_in[5];
    const float* gk    = (const float*)d_in[6];
    const float* Wout  = (const float*)d_in[7];
    const float* bout  = (const float*)d_in[8];
    float* out = (float*)d_out;

    void* p_qkv; cudaGetSymbolAddress(&p_qkv, g_qkv);
    void* p_o;   cudaGetSymbolAddress(&p_o,   g_o);
    void* p_q;   cudaGetSymbolAddress(&p_q,   g_q);
    void* p_k;   cudaGetSymbolAddress(&p_k,   g_k);
    void* p_s;   cudaGetSymbolAddress(&p_s,   g_scores);
    void* p_vt;  cudaGetSymbolAddress(&p_vt,  g_vt);
    void* p_wq;  cudaGetSymbolAddress(&p_wq,  g_wq);
    void* p_wo;  cudaGetSymbolAddress(&p_wo,  g_wo);
    void* p_x;   cudaGetSymbolAddress(&p_x,   g_x);

    static int smem_set = 0;
    if (!smem_set) {
        cudaFuncSetAttribute(tc_gemm, cudaFuncAttributeMaxDynamicSharedMemorySize, GEMM_SMEM);
        smem_set = 1;
    }

    // 0) weight transpose + tf32 rounding; activation rounding
    cvtT_kernel<<<dim3(QKVDIM / 32, DIMM / 32), dim3(32, 8)>>>(Wqkv, (float*)p_wq, DIMM, QKVDIM);
    cvtT_kernel<<<dim3(DIMM / 32,  DIMM / 32), dim3(32, 8)>>>(Wout, (float*)p_wo, DIMM, DIMM);
    {
        size_t n4 = (size_t)TOKENS * DIMM / 4;
        cvt_rna_kernel<<<(unsigned)((n4 + 255) / 256), 256>>>(x, (float*)p_x, n4);
    }

    // 1) QKV projection  (grid: x = M tiles, y = N tiles)
    tc_gemm<<<dim3(TOKENS / 128, QKVDIM / 128, 1), 256, GEMM_SMEM>>>(
        (const float*)p_x, (const float*)p_wq, bqkv, (float*)p_qkv,
        0, 0, 0, DIMM, DIMM, QKVDIM, DIMM, 1.f, 0);

    // 2) RMSNorm + RoPE (tf32 out), V transpose (tf32 out)
    rmsrope_kernel<<<TOKENS, 256>>>(cosb, sinb, gq, gk);
    vtrans_kernel<<<dim3(LL / 32, HDIM / 32, BB * NHEADS), dim3(32, 8)>>>();

    // 3) scores = SCALE * q k^T  (z = head, per batch)
    for (int b = 0; b < BB; b++) {
        tc_gemm<<<dim3(LL / 128, LL / 128, NHEADS), 256, GEMM_SMEM>>>(
            (const float*)p_q + (size_t)b * LL * DIMM,
            (const float*)p_k + (size_t)b * LL * DIMM,
            nullptr,
            (float*)p_s + (size_t)b * NHEADS * LL * LL,
            HDIM, HDIM, (long)LL * LL,
            DIMM, DIMM, LL, HDIM, SCALE, 0);
    }

    // 4) softmax (tf32-rounded probs)
    softmax_kernel<<<BB * NHEADS * LL, 256>>>();

    // 5) o = P V  (z = head, per batch); tf32-rounded out
    for (int b = 0; b < BB; b++) {
        tc_gemm<<<dim3(LL / 128, HDIM / 128, NHEADS), 256, GEMM_SMEM>>>(
            (const float*)p_s + (size_t)b * NHEADS * LL * LL,
            (const float*)p_vt + (size_t)b * NHEADS * HDIM * LL,
            nullptr,
            (float*)p_o + (size_t)b * LL * DIMM,
            (long)LL * LL, (long)HDIM * LL, HDIM,
            LL, LL, DIMM, LL, 1.f, 1);
    }

    // 6) out projection
    tc_gemm<<<dim3(TOKENS / 128, DIMM / 128, 1), 256, GEMM_SMEM>>>(
        (const float*)p_o, (const float*)p_wo, bout, out,
        0, 0, 0, DIMM, DIMM, DIMM, DIMM, 1.f, 0);
}

// round 6
// speedup vs baseline: 4.2438x; 1.0461x over previous
#include <cuda_runtime.h>
#include <cuda_bf16.h>
#include <math.h>
#include <stdint.h>

// Problem constants
#define DIMM 5120
#define NHEADS 40
#define HDIM 128
#define BB 2
#define LL 1024
#define TOKENS (BB*LL)          // 2048
#define QKVDIM (3*DIMM)         // 15360
#define SCALE 0.08838834764831845f
#define EPS 1e-6f

// -------- scratch (static device globals; no runtime allocation) --------
__device__ float g_qkv[(size_t)TOKENS * QKVDIM];          // 125.8 MB
__device__ float g_q[(size_t)TOKENS * DIMM];
__device__ float g_k[(size_t)TOKENS * DIMM];
__device__ float g_scores[(size_t)BB * NHEADS * LL * LL]; // 335.5 MB
__device__ float g_o[(size_t)TOKENS * DIMM];
__device__ float g_vt[(size_t)BB * NHEADS * HDIM * LL];   // V^T per head, tf32
__device__ float g_wq[(size_t)QKVDIM * DIMM];             // W_qkv^T tf32 [N,K]
__device__ float g_wo[(size_t)DIMM * DIMM];               // W_out^T tf32 [N,K]
__device__ float g_x[(size_t)TOKENS * DIMM];              // x tf32-rounded

// ============================================================
// helpers
// ============================================================
__device__ __forceinline__ uint32_t smem_u32(const void* p) {
    uint32_t a;
    asm("{ .reg .u64 t; cvta.to.shared.u64 t, %1; cvt.u32.u64 %0, t; }" : "=r"(a) : "l"(p));
    return a;
}
__device__ __forceinline__ float tf32r(float x) {
    float y; asm("cvt.rna.tf32.f32 %0, %1;" : "=f"(y) : "f"(x)); return y;
}
__device__ __forceinline__ void cpa16(uint32_t dst, const void* src) {
    asm volatile("cp.async.cg.shared.global [%0], [%1], 16;" :: "r"(dst), "l"(src));
}
#define CPA_COMMIT() asm volatile("cp.async.commit_group;" ::: "memory")
#define CPA_WAIT1()  asm volatile("cp.async.wait_group 1;" ::: "memory")
#define CPA_WAIT0()  asm volatile("cp.async.wait_group 0;" ::: "memory")

__device__ __forceinline__ void mma1688(float* d, const uint32_t* a, uint32_t b0, uint32_t b1) {
    asm volatile(
        "mma.sync.aligned.m16n8k8.row.col.f32.tf32.tf32.f32 "
        "{%0,%1,%2,%3}, {%4,%5,%6,%7}, {%8,%9}, {%0,%1,%2,%3};"
        : "+f"(d[0]), "+f"(d[1]), "+f"(d[2]), "+f"(d[3])
        : "r"(a[0]), "r"(a[1]), "r"(a[2]), "r"(a[3]), "r"(b0), "r"(b1));
}

// ldmatrix x4: four 8x8 b16 tiles (= 8x4 tf32 tiles)
__device__ __forceinline__ void ldsm4(uint32_t* r, uint32_t addr) {
    asm volatile("ldmatrix.sync.aligned.m8n8.x4.shared.b16 {%0,%1,%2,%3}, [%4];"
        : "=r"(r[0]), "=r"(r[1]), "=r"(r[2]), "=r"(r[3]) : "r"(addr));
}

// ============================================================
// Generalized tf32 mma.sync GEMM:
//   C[z][m,n] = alpha * A[z][m,:K] * Bt[z][n,:K]^T (+ bias[n])
// CTA tile 128x128, K-chunk 32, 3-stage cp.async pipeline.
// Fragments via ldmatrix.x4 (24 LDSM per warp-chunk vs 96 scalar LDS).
// Grid: blockIdx.x = M tile, blockIdx.y = N tile.
// smem rows stride 36 floats (144B) -> ldmatrix conflict-free.
// ============================================================
#define KC2 32
#define TST 36
#define TST4 (TST*4)
#define TILE_F (128 * TST)                 // 4608 floats per tile
#define STAGE_F (2 * TILE_F)               // A tile + B tile
#define NSTG 3
#define GEMM_SMEM (NSTG * STAGE_F * 4)     // 110592 bytes

__global__ __launch_bounds__(256) void tc_gemm(
    const float* __restrict__ A, const float* __restrict__ Bt,
    const float* __restrict__ bias, float* __restrict__ C,
    long sAz, long sBz, long sCz,
    int lda, int ldb, int ldc, int K, float alpha, int round_out)
{
    extern __shared__ float sm[];
    const uint32_t sb = smem_u32(sm);

    A  += (size_t)blockIdx.z * sAz;
    Bt += (size_t)blockIdx.z * sBz;
    C  += (size_t)blockIdx.z * sCz;

    const int tid  = threadIdx.x;
    const int warp = tid >> 5;
    const int lane = tid & 31;
    const int wm = warp >> 2;          // 0..1
    const int wn = warp & 3;           // 0..3
    const int m0 = blockIdx.x * 128;
    const int n0 = blockIdx.y * 128;

    // cp.async mapping: 1024 16B-granules per tile, 4 per thread
    const int grow = tid >> 3;         // +32*i
    const int gc4  = (tid & 7) * 4;    // 0..28

    // ldmatrix per-lane byte offsets
    // A: rows (l&15), k-seg (l>>4)*4 floats
    const uint32_t aOff = (uint32_t)(lane & 15) * TST4 + (uint32_t)(lane >> 4) * 16;
    // B: rows (l&7)+8*((l>>4)&1), k-seg ((l>>3)&1)*4 floats
    const uint32_t bOff = (uint32_t)((lane & 7) + ((lane >> 4) & 1) * 8) * TST4
                        + (uint32_t)((lane >> 3) & 1) * 16;

    float acc[4][4][4];
#pragma unroll
    for (int mt = 0; mt < 4; mt++)
#pragma unroll
        for (int nt = 0; nt < 4; nt++)
#pragma unroll
            for (int r = 0; r < 4; r++) acc[mt][nt][r] = 0.f;

    const int nch = K / KC2;

    auto load_chunk = [&](int st, int kc) {
        uint32_t base = sb + (uint32_t)st * (STAGE_F * 4);
#pragma unroll
        for (int i = 0; i < 4; i++) {
            int row = grow + i * 32;
            uint32_t off = (uint32_t)(row * TST + gc4) * 4;
            cpa16(base + off,                A + (size_t)(m0 + row) * lda + kc + gc4);
            cpa16(base + TILE_F * 4 + off,   Bt + (size_t)(n0 + row) * ldb + kc + gc4);
        }
    };

    load_chunk(0, 0);       CPA_COMMIT();
    if (nch > 1) { load_chunk(1, KC2); CPA_COMMIT(); }

    for (int c = 0; c < nch; c++) {
        const int st = c % NSTG;
        if (c + 1 < nch) { CPA_WAIT1(); } else { CPA_WAIT0(); }
        __syncthreads();
        if (c + 2 < nch) { load_chunk((c + 2) % NSTG, (c + 2) * KC2); CPA_COMMIT(); }

        const uint32_t aBase = sb + (uint32_t)st * (STAGE_F * 4)
                             + (uint32_t)(wm * 64) * TST4 + aOff;
        const uint32_t bBase = sb + (uint32_t)st * (STAGE_F * 4) + TILE_F * 4
                             + (uint32_t)(wn * 32) * TST4 + bOff;

#pragma unroll
        for (int s = 0; s < 4; s++) {
            const uint32_t k8b = (uint32_t)s * 32;   // 8 floats = 32 bytes
            uint32_t af[4][4];
#pragma unroll
            for (int mt = 0; mt < 4; mt++)
                ldsm4(af[mt], aBase + (uint32_t)(mt * 16) * TST4 + k8b);
            uint32_t bf[2][4];
#pragma unroll
            for (int np = 0; np < 2; np++)
                ldsm4(bf[np], bBase + (uint32_t)(np * 16) * TST4 + k8b);
#pragma unroll
            for (int mt = 0; mt < 4; mt++)
#pragma unroll
                for (int nt = 0; nt < 4; nt++)
                    mma1688(acc[mt][nt], af[mt],
                            bf[nt >> 1][(nt & 1) * 2], bf[nt >> 1][(nt & 1) * 2 + 1]);
        }
    }

    // epilogue
    {
        const int r = lane >> 2, cq = lane & 3;
#pragma unroll
        for (int mt = 0; mt < 4; mt++) {
            int row = m0 + wm * 64 + mt * 16 + r;
#pragma unroll
            for (int nt = 0; nt < 4; nt++) {
                int col = n0 + wn * 32 + nt * 8 + 2 * cq;
                float2 bv = make_float2(0.f, 0.f);
                if (bias) bv = *(const float2*)(bias + col);
                float o0x = fmaf(acc[mt][nt][0], alpha, bv.x);
                float o0y = fmaf(acc[mt][nt][1], alpha, bv.y);
                float o1x = fmaf(acc[mt][nt][2], alpha, bv.x);
                float o1y = fmaf(acc[mt][nt][3], alpha, bv.y);
                if (round_out) { o0x = tf32r(o0x); o0y = tf32r(o0y);
                                 o1x = tf32r(o1x); o1y = tf32r(o1y); }
                *(float2*)(C + (size_t)row * ldc + col) = make_float2(o0x, o0y);
                *(float2*)(C + (size_t)(row + 8) * ldc + col) = make_float2(o1x, o1y);
            }
        }
    }
}

// ============================================================
// convert helpers
// ============================================================
__global__ void cvt_rna_kernel(const float* __restrict__ s, float* __restrict__ d, size_t n4)
{
    size_t i = (size_t)blockIdx.x * blockDim.x + threadIdx.x;
    if (i < n4) {
        float4 v = ((const float4*)s)[i];
        v.x = tf32r(v.x); v.y = tf32r(v.y); v.z = tf32r(v.z); v.w = tf32r(v.w);
        ((float4*)d)[i] = v;
    }
}

__global__ void cvtT_kernel(const float* __restrict__ src, float* __restrict__ dst,
                            int K, int N)
{
    __shared__ float tile[32][33];
    int k0 = blockIdx.y * 32, n0 = blockIdx.x * 32;
    int tx = threadIdx.x, ty = threadIdx.y;  // 32 x 8
#pragma unroll
    for (int i = 0; i < 32; i += 8)
        tile[ty + i][tx] = src[(size_t)(k0 + ty + i) * N + n0 + tx];
    __syncthreads();
#pragma unroll
    for (int i = 0; i < 32; i += 8)
        dst[(size_t)(n0 + ty + i) * K + k0 + tx] = tf32r(tile[tx][ty + i]);
}

// V^T per head: g_vt[bh][d][k] = tf32r(v[b,k,h,d]). grid (32,4,80), block (32,8)
__global__ void vtrans_kernel()
{
    __shared__ float tile[32][33];
    const int bh = blockIdx.z;
    const int b = bh / NHEADS, h = bh % NHEADS;
    const int k0 = blockIdx.x * 32, d0 = blockIdx.y * 32;
    const float* src = g_qkv + (size_t)b * LL * QKVDIM + 2 * DIMM + h * HDIM;
    float* dst = g_vt + (size_t)bh * HDIM * LL;
    int tx = threadIdx.x, ty = threadIdx.y;
#pragma unroll
    for (int i = 0; i < 32; i += 8)
        tile[ty + i][tx] = src[(size_t)(k0 + ty + i) * QKVDIM + d0 + tx];
    __syncthreads();
#pragma unroll
    for (int i = 0; i < 32; i += 8)
        dst[(size_t)(d0 + ty + i) * LL + k0 + tx] = tf32r(tile[tx][ty + i]);
}

// ============================================================
// RMSNorm + gain + RoPE -> tf32-rounded q,k
// ============================================================
__global__ __launch_bounds__(256) void rmsrope_kernel(
    const float* __restrict__ cosb, const float* __restrict__ sinb,
    const float* __restrict__ gq, const float* __restrict__ gk)
{
    const int t = blockIdx.x;
    const int tid = threadIdx.x;
    const float* base = g_qkv + (size_t)t * QKVDIM;

    float sq = 0.f, sk = 0.f;
    for (int i = tid; i < DIMM; i += 256) {
        float a = base[i];         sq = fmaf(a, a, sq);
        float b = base[DIMM + i];  sk = fmaf(b, b, sk);
    }
    __shared__ float r1[256], r2[256];
    r1[tid] = sq; r2[tid] = sk;
    __syncthreads();
    for (int s = 128; s > 0; s >>= 1) {
        if (tid < s) { r1[tid] += r1[tid + s]; r2[tid] += r2[tid + s]; }
        __syncthreads();
    }
    const float rq = rsqrtf(r1[0] / (float)DIMM + EPS);
    const float rk = rsqrtf(r2[0] / (float)DIMM + EPS);

    const int l = t & (LL - 1);
    const float* cl = cosb + (size_t)l * HDIM;
    const float* sl = sinb + (size_t)l * HDIM;
    float* qo = g_q + (size_t)t * DIMM;
    float* ko = g_k + (size_t)t * DIMM;

    for (int p = tid; p < DIMM / 2; p += 256) {
        int d = 2 * p;
        int hd = d & (HDIM - 1);
        float c = cl[hd];
        float s = sl[hd + 1];
        float x0 = base[d]     * rq * gq[d];
        float x1 = base[d + 1] * rq * gq[d + 1];
        qo[d]     = tf32r(x0 * c - x1 * s);
        qo[d + 1] = tf32r(x0 * s + x1 * c);
        float y0 = base[DIMM + d]     * rk * gk[d];
        float y1 = base[DIMM + d + 1] * rk * gk[d + 1];
        ko[d]     = tf32r(y0 * c - y1 * s);
        ko[d + 1] = tf32r(y0 * s + y1 * c);
    }
}

// ============================================================
// softmax over last dim (1024); stores tf32-rounded probs
// ============================================================
__global__ __launch_bounds__(256) void softmax_kernel()
{
    __shared__ float red[256];
    float* row = g_scores + (size_t)blockIdx.x * LL;
    const int tid = threadIdx.x;

    float4 v = ((float4*)row)[tid];
    float m = fmaxf(fmaxf(v.x, v.y), fmaxf(v.z, v.w));
    red[tid] = m;
    __syncthreads();
    for (int s = 128; s > 0; s >>= 1) {
        if (tid < s) red[tid] = fmaxf(red[tid], red[tid + s]);
        __syncthreads();
    }
    m = red[0];
    __syncthreads();

    v.x = expf(v.x - m); v.y = expf(v.y - m);
    v.z = expf(v.z - m); v.w = expf(v.w - m);
    red[tid] = v.x + v.y + v.z + v.w;
    __syncthreads();
    for (int s = 128; s > 0; s >>= 1) {
        if (tid < s) red[tid] += red[tid + s];
        __syncthreads();
    }
    float inv = 1.f / red[0];
    v.x = tf32r(v.x * inv); v.y = tf32r(v.y * inv);
    v.z = tf32r(v.z * inv); v.w = tf32r(v.w * inv);
    ((float4*)row)[tid] = v;
}

// ============================================================
// launch
// ============================================================
extern "C" void kernel_launch(void* const* d_in, const int* in_sizes, int n_in,
                              void* d_out, int out_size)
{
    const float* x     = (const float*)d_in[0];
    const float* cosb  = (const float*)d_in[1];
    const float* sinb  = (const float*)d_in[2];
    const float* Wqkv  = (const float*)d_in[3];
    const float* bqkv  = (const float*)d_in[4];
    const float* gq    = (const float*)d_in[5];
    const float* gk    = (const float*)d_in[6];
    const float* Wout  = (const float*)d_in[7];
    const float* bout  = (const float*)d_in[8];
    float* out = (float*)d_out;

    void* p_qkv; cudaGetSymbolAddress(&p_qkv, g_qkv);
    void* p_o;   cudaGetSymbolAddress(&p_o,   g_o);
    void* p_q;   cudaGetSymbolAddress(&p_q,   g_q);
    void* p_k;   cudaGetSymbolAddress(&p_k,   g_k);
    void* p_s;   cudaGetSymbolAddress(&p_s,   g_scores);
    void* p_vt;  cudaGetSymbolAddress(&p_vt,  g_vt);
    void* p_wq;  cudaGetSymbolAddress(&p_wq,  g_wq);
    void* p_wo;  cudaGetSymbolAddress(&p_wo,  g_wo);
    void* p_x;   cudaGetSymbolAddress(&p_x,   g_x);

    cudaFuncSetAttribute(tc_gemm, cudaFuncAttributeMaxDynamicSharedMemorySize, GEMM_SMEM);

    // 0) weight transpose + tf32 rounding; activation rounding
    cvtT_kernel<<<dim3(QKVDIM / 32, DIMM / 32), dim3(32, 8)>>>(Wqkv, (float*)p_wq, DIMM, QKVDIM);
    cvtT_kernel<<<dim3(DIMM / 32,  DIMM / 32), dim3(32, 8)>>>(Wout, (float*)p_wo, DIMM, DIMM);
    {
        size_t n4 = (size_t)TOKENS * DIMM / 4;
        cvt_rna_kernel<<<(unsigned)((n4 + 255) / 256), 256>>>(x, (float*)p_x, n4);
    }

    // 1) QKV projection  (grid: x = M tiles, y = N tiles)
    tc_gemm<<<dim3(TOKENS / 128, QKVDIM / 128, 1), 256, GEMM_SMEM>>>(
        (const float*)p_x, (const float*)p_wq, bqkv, (float*)p_qkv,
        0, 0, 0, DIMM, DIMM, QKVDIM, DIMM, 1.f, 0);

    // 2) RMSNorm + RoPE (tf32 out), V transpose (tf32 out)
    rmsrope_kernel<<<TOKENS, 256>>>(cosb, sinb, gq, gk);
    vtrans_kernel<<<dim3(LL / 32, HDIM / 32, BB * NHEADS), dim3(32, 8)>>>();

    // 3) scores = SCALE * q k^T  (z = head, per batch)
    for (int b = 0; b < BB; b++) {
        tc_gemm<<<dim3(LL / 128, LL / 128, NHEADS), 256, GEMM_SMEM>>>(
            (const float*)p_q + (size_t)b * LL * DIMM,
            (const float*)p_k + (size_t)b * LL * DIMM,
            nullptr,
            (float*)p_s + (size_t)b * NHEADS * LL * LL,
            HDIM, HDIM, (long)LL * LL,
            DIMM, DIMM, LL, HDIM, SCALE, 0);
    }

    // 4) softmax (tf32-rounded probs)
    softmax_kernel<<<BB * NHEADS * LL, 256>>>();

    // 5) o = P V  (z = head, per batch); tf32-rounded out
    for (int b = 0; b < BB; b++) {
        tc_gemm<<<dim3(LL / 128, HDIM / 128, NHEADS), 256, GEMM_SMEM>>>(
            (const float*)p_s + (size_t)b * NHEADS * LL * LL,
            (const float*)p_vt + (size_t)b * NHEADS * HDIM * LL,
            nullptr,
            (float*)p_o + (size_t)b * LL * DIMM,
            (long)LL * LL, (long)HDIM * LL, HDIM,
            LL, LL, DIMM, LL, 1.f, 1);
    }

    // 6) out projection
    tc_gemm<<<dim3(TOKENS / 128, DIMM / 128, 1), 256, GEMM_SMEM>>>(
        (const float*)p_o, (const float*)p_wo, bout, out,
        0, 0, 0, DIMM, DIMM, DIMM, DIMM, 1.f, 0);
}

// round 7
// speedup vs baseline: 7.6486x; 1.8023x over previous
#include <cuda_runtime.h>
#include <cuda_fp16.h>
#include <math.h>
#include <stdint.h>

// Problem constants
#define DIMM 5120
#define NHEADS 40
#define HDIM 128
#define BB 2
#define LL 1024
#define TOKENS (BB*LL)          // 2048
#define QKVDIM (3*DIMM)         // 15360
#define SCALE 0.08838834764831845f
#define EPS 1e-6f

// -------- scratch (static device globals; no runtime allocation) --------
__device__ float  g_qkv[(size_t)TOKENS * QKVDIM];           // 125.8 MB f32
__device__ float  g_scores[(size_t)BB * NHEADS * LL * LL];  // 335.5 MB f32
__device__ __half g_p[(size_t)BB * NHEADS * LL * LL];       // probs, half
__device__ __half g_q[(size_t)TOKENS * DIMM];
__device__ __half g_k[(size_t)TOKENS * DIMM];
__device__ __half g_o[(size_t)TOKENS * DIMM];
__device__ __half g_vt[(size_t)BB * NHEADS * HDIM * LL];    // V^T per head
__device__ __half g_wq[(size_t)QKVDIM * DIMM];              // W_qkv^T [N,K]
__device__ __half g_wo[(size_t)DIMM * DIMM];                // W_out^T [N,K]
__device__ __half g_x[(size_t)TOKENS * DIMM];               // x, half

// ============================================================
// helpers
// ============================================================
__device__ __forceinline__ uint32_t smem_u32(const void* p) {
    uint32_t a;
    asm("{ .reg .u64 t; cvta.to.shared.u64 t, %1; cvt.u32.u64 %0, t; }" : "=r"(a) : "l"(p));
    return a;
}
__device__ __forceinline__ void cpa16(uint32_t dst, const void* src) {
    asm volatile("cp.async.cg.shared.global [%0], [%1], 16;" :: "r"(dst), "l"(src));
}
#define CPA_COMMIT() asm volatile("cp.async.commit_group;" ::: "memory")
#define CPA_WAIT1()  asm volatile("cp.async.wait_group 1;" ::: "memory")
#define CPA_WAIT0()  asm volatile("cp.async.wait_group 0;" ::: "memory")

// fp16 m16n8k16, f32 accum
__device__ __forceinline__ void mma16816(float* d, const uint32_t* a, uint32_t b0, uint32_t b1) {
    asm volatile(
        "mma.sync.aligned.m16n8k16.row.col.f32.f16.f16.f32 "
        "{%0,%1,%2,%3}, {%4,%5,%6,%7}, {%8,%9}, {%0,%1,%2,%3};"
        : "+f"(d[0]), "+f"(d[1]), "+f"(d[2]), "+f"(d[3])
        : "r"(a[0]), "r"(a[1]), "r"(a[2]), "r"(a[3]), "r"(b0), "r"(b1));
}
__device__ __forceinline__ void ldsm4(uint32_t* r, uint32_t addr) {
    asm volatile("ldmatrix.sync.aligned.m8n8.x4.shared.b16 {%0,%1,%2,%3}, [%4];"
        : "=r"(r[0]), "=r"(r[1]), "=r"(r[2]), "=r"(r[3]) : "r"(addr));
}

// ============================================================
// fp16 mma.sync GEMM:
//   C[z][m,n] = alpha * A[z][m,:K] * Bt[z][n,:K]^T (+ bias[n])
// A, Bt: __half row-major (K contiguous). C: float, or half if store_half.
// CTA tile 128x128, K-chunk 64 (128B rows), 3-stage cp.async pipeline.
// smem rows: 64 halves + 8 pad = 144 B -> bank-conflict-free ldmatrix.
// Grid: blockIdx.x = M tile, blockIdx.y = N tile, z batched.
// ============================================================
#define KC 64
#define ROWB 144                            // bytes per smem row
#define TILE_B (128 * ROWB)                 // 18432 B per tile
#define STAGE_B (2 * TILE_B)                // 36864 B (A + B tiles)
#define NSTG 3
#define GEMM_SMEM (NSTG * STAGE_B)          // 110592 B

__global__ __launch_bounds__(256) void tc_gemm(
    const __half* __restrict__ A, const __half* __restrict__ Bt,
    const float* __restrict__ bias, void* __restrict__ Cv,
    long sAz, long sBz, long sCz,
    int lda, int ldb, int ldc, int K, float alpha, int store_half)
{
    extern __shared__ char sm[];
    const uint32_t sb = smem_u32(sm);

    A  += (size_t)blockIdx.z * sAz;
    Bt += (size_t)blockIdx.z * sBz;

    const int tid  = threadIdx.x;
    const int warp = tid >> 5;
    const int lane = tid & 31;
    const int wm = warp >> 2;          // 0..1
    const int wn = warp & 3;           // 0..3
    const int m0 = blockIdx.x * 128;
    const int n0 = blockIdx.y * 128;

    // cp.async: 1024 granules (16B) per tile, 4 per thread
    const int grow = tid >> 1;                   // base rows via op>>3
    (void)grow;

    // ldmatrix per-lane byte offsets (row stride 144B)
    // A: row (l&15), k-half (l>>4)*16B
    const uint32_t aOff = (uint32_t)(lane & 15) * ROWB + (uint32_t)(lane >> 4) * 16;
    // B: row (l&7)+((l>>4)&1)*8, k-half ((l>>3)&1)*16B
    const uint32_t bOff = (uint32_t)((lane & 7) + ((lane >> 4) & 1) * 8) * ROWB
                        + (uint32_t)((lane >> 3) & 1) * 16;

    float acc[4][4][4];
#pragma unroll
    for (int mt = 0; mt < 4; mt++)
#pragma unroll
        for (int nt = 0; nt < 4; nt++)
#pragma unroll
            for (int r = 0; r < 4; r++) acc[mt][nt][r] = 0.f;

    const int nch = K / KC;

    auto load_chunk = [&](int st, int kc) {
        uint32_t base = sb + (uint32_t)st * STAGE_B;
#pragma unroll
        for (int i = 0; i < 4; i++) {
            int op = tid + i * 256;
            int row = op >> 3, g = op & 7;
            uint32_t off = (uint32_t)row * ROWB + (uint32_t)g * 16;
            cpa16(base + off,
                  (const char*)A + ((size_t)(m0 + row) * lda + kc + g * 8) * 2);
            cpa16(base + TILE_B + off,
                  (const char*)Bt + ((size_t)(n0 + row) * ldb + kc + g * 8) * 2);
        }
    };

    load_chunk(0, 0);       CPA_COMMIT();
    if (nch > 1) { load_chunk(1, KC); CPA_COMMIT(); }

    for (int c = 0; c < nch; c++) {
        const int st = c % NSTG;
        if (c + 1 < nch) { CPA_WAIT1(); } else { CPA_WAIT0(); }
        __syncthreads();
        if (c + 2 < nch) { load_chunk((c + 2) % NSTG, (c + 2) * KC); CPA_COMMIT(); }

        const uint32_t aBase = sb + (uint32_t)st * STAGE_B
                             + (uint32_t)(wm * 64) * ROWB + aOff;
        const uint32_t bBase = sb + (uint32_t)st * STAGE_B + TILE_B
                             + (uint32_t)(wn * 32) * ROWB + bOff;

#pragma unroll
        for (int s = 0; s < 4; s++) {               // 4 x k16 per chunk
            const uint32_t kb = (uint32_t)s * 32;   // 16 halves = 32 bytes
            uint32_t af[4][4];
#pragma unroll
            for (int mt = 0; mt < 4; mt++)
                ldsm4(af[mt], aBase + (uint32_t)(mt * 16) * ROWB + kb);
            uint32_t bf[2][4];
#pragma unroll
            for (int np = 0; np < 2; np++)
                ldsm4(bf[np], bBase + (uint32_t)(np * 16) * ROWB + kb);
#pragma unroll
            for (int mt = 0; mt < 4; mt++)
#pragma unroll
                for (int nt = 0; nt < 4; nt++)
                    mma16816(acc[mt][nt], af[mt],
                             bf[nt >> 1][(nt & 1) * 2], bf[nt >> 1][(nt & 1) * 2 + 1]);
        }
    }

    // epilogue (m16n8 layout identical to k8 variant)
    {
        const int r = lane >> 2, cq = lane & 3;
#pragma unroll
        for (int mt = 0; mt < 4; mt++) {
            int row = m0 + wm * 64 + mt * 16 + r;
#pragma unroll
            for (int nt = 0; nt < 4; nt++) {
                int col = n0 + wn * 32 + nt * 8 + 2 * cq;
                float bvx = 0.f, bvy = 0.f;
                if (bias) { float2 bv = *(const float2*)(bias + col); bvx = bv.x; bvy = bv.y; }
                float o0x = fmaf(acc[mt][nt][0], alpha, bvx);
                float o0y = fmaf(acc[mt][nt][1], alpha, bvy);
                float o1x = fmaf(acc[mt][nt][2], alpha, bvx);
                float o1y = fmaf(acc[mt][nt][3], alpha, bvy);
                if (store_half) {
                    __half* C = (__half*)Cv + (size_t)blockIdx.z * sCz;
                    *(__half2*)(C + (size_t)row * ldc + col) =
                        __floats2half2_rn(o0x, o0y);
                    *(__half2*)(C + (size_t)(row + 8) * ldc + col) =
                        __floats2half2_rn(o1x, o1y);
                } else {
                    float* C = (float*)Cv + (size_t)blockIdx.z * sCz;
                    *(float2*)(C + (size_t)row * ldc + col) = make_float2(o0x, o0y);
                    *(float2*)(C + (size_t)(row + 8) * ldc + col) = make_float2(o1x, o1y);
                }
            }
        }
    }
}

// ============================================================
// convert helpers
// ============================================================
__global__ void cvt_h_kernel(const float* __restrict__ s, __half* __restrict__ d, size_t n4)
{
    size_t i = (size_t)blockIdx.x * blockDim.x + threadIdx.x;
    if (i < n4) {
        float4 v = ((const float4*)s)[i];
        __half2 h0 = __floats2half2_rn(v.x, v.y);
        __half2 h1 = __floats2half2_rn(v.z, v.w);
        ((__half2*)d)[2 * i] = h0;
        ((__half2*)d)[2 * i + 1] = h1;
    }
}

// transpose [K,N] -> [N,K] with fp16 rounding
__global__ void cvtT_kernel(const float* __restrict__ src, __half* __restrict__ dst,
                            int K, int N)
{
    __shared__ float tile[32][33];
    int k0 = blockIdx.y * 32, n0 = blockIdx.x * 32;
    int tx = threadIdx.x, ty = threadIdx.y;  // 32 x 8
#pragma unroll
    for (int i = 0; i < 32; i += 8)
        tile[ty + i][tx] = src[(size_t)(k0 + ty + i) * N + n0 + tx];
    __syncthreads();
#pragma unroll
    for (int i = 0; i < 32; i += 8)
        dst[(size_t)(n0 + ty + i) * K + k0 + tx] = __float2half_rn(tile[tx][ty + i]);
}

// V^T per head: g_vt[bh][d][k] = half(v[b,k,h,d]). grid (32,4,80), block (32,8)
__global__ void vtrans_kernel()
{
    __shared__ float tile[32][33];
    const int bh = blockIdx.z;
    const int b = bh / NHEADS, h = bh % NHEADS;
    const int k0 = blockIdx.x * 32, d0 = blockIdx.y * 32;
    const float* src = g_qkv + (size_t)b * LL * QKVDIM + 2 * DIMM + h * HDIM;
    __half* dst = g_vt + (size_t)bh * HDIM * LL;
    int tx = threadIdx.x, ty = threadIdx.y;
#pragma unroll
    for (int i = 0; i < 32; i += 8)
        tile[ty + i][tx] = src[(size_t)(k0 + ty + i) * QKVDIM + d0 + tx];
    __syncthreads();
#pragma unroll
    for (int i = 0; i < 32; i += 8)
        dst[(size_t)(d0 + ty + i) * LL + k0 + tx] = __float2half_rn(tile[tx][ty + i]);
}

// ============================================================
// RMSNorm + gain + RoPE -> half q,k
// ============================================================
__global__ __launch_bounds__(256) void rmsrope_kernel(
    const float* __restrict__ cosb, const float* __restrict__ sinb,
    const float* __restrict__ gq, const float* __restrict__ gk)
{
    const int t = blockIdx.x;
    const int tid = threadIdx.x;
    const float* base = g_qkv + (size_t)t * QKVDIM;

    float sq = 0.f, sk = 0.f;
    for (int i = tid; i < DIMM; i += 256) {
        float a = base[i];         sq = fmaf(a, a, sq);
        float b = base[DIMM + i];  sk = fmaf(b, b, sk);
    }
    __shared__ float r1[256], r2[256];
    r1[tid] = sq; r2[tid] = sk;
    __syncthreads();
    for (int s = 128; s > 0; s >>= 1) {
        if (tid < s) { r1[tid] += r1[tid + s]; r2[tid] += r2[tid + s]; }
        __syncthreads();
    }
    const float rq = rsqrtf(r1[0] / (float)DIMM + EPS);
    const float rk = rsqrtf(r2[0] / (float)DIMM + EPS);

    const int l = t & (LL - 1);
    const float* cl = cosb + (size_t)l * HDIM;
    const float* sl = sinb + (size_t)l * HDIM;
    __half* qo = g_q + (size_t)t * DIMM;
    __half* ko = g_k + (size_t)t * DIMM;

    for (int p = tid; p < DIMM / 2; p += 256) {
        int d = 2 * p;
        int hd = d & (HDIM - 1);
        float c = cl[hd];
        float s = sl[hd + 1];
        float x0 = base[d]     * rq * gq[d];
        float x1 = base[d + 1] * rq * gq[d + 1];
        *(__half2*)(qo + d) = __floats2half2_rn(x0 * c - x1 * s, x0 * s + x1 * c);
        float y0 = base[DIMM + d]     * rk * gk[d];
        float y1 = base[DIMM + d + 1] * rk * gk[d + 1];
        *(__half2*)(ko + d) = __floats2half2_rn(y0 * c - y1 * s, y0 * s + y1 * c);
    }
}

// ============================================================
// softmax over last dim (1024); reads f32 scores, writes half probs
// ============================================================
__global__ __launch_bounds__(256) void softmax_kernel()
{
    __shared__ float red[256];
    const float* row = g_scores + (size_t)blockIdx.x * LL;
    __half* prow = g_p + (size_t)blockIdx.x * LL;
    const int tid = threadIdx.x;

    float4 v = ((const float4*)row)[tid];
    float m = fmaxf(fmaxf(v.x, v.y), fmaxf(v.z, v.w));
    red[tid] = m;
    __syncthreads();
    for (int s = 128; s > 0; s >>= 1) {
        if (tid < s) red[tid] = fmaxf(red[tid], red[tid + s]);
        __syncthreads();
    }
    m = red[0];
    __syncthreads();

    v.x = expf(v.x - m); v.y = expf(v.y - m);
    v.z = expf(v.z - m); v.w = expf(v.w - m);
    red[tid] = v.x + v.y + v.z + v.w;
    __syncthreads();
    for (int s = 128; s > 0; s >>= 1) {
        if (tid < s) red[tid] += red[tid + s];
        __syncthreads();
    }
    float inv = 1.f / red[0];
    ((__half2*)prow)[2 * tid]     = __floats2half2_rn(v.x * inv, v.y * inv);
    ((__half2*)prow)[2 * tid + 1] = __floats2half2_rn(v.z * inv, v.w * inv);
}

// ============================================================
// launch
// ============================================================
extern "C" void kernel_launch(void* const* d_in, const int* in_sizes, int n_in,
                              void* d_out, int out_size)
{
    const float* x     = (const float*)d_in[0];
    const float* cosb  = (const float*)d_in[1];
    const float* sinb  = (const float*)d_in[2];
    const float* Wqkv  = (const float*)d_in[3];
    const float* bqkv  = (const float*)d_in[4];
    const float* gq    = (const float*)d_in[5];
    const float* gk    = (const float*)d_in[6];
    const float* Wout  = (const float*)d_in[7];
    const float* bout  = (const float*)d_in[8];
    float* out = (float*)d_out;

    void* p_qkv; cudaGetSymbolAddress(&p_qkv, g_qkv);
    void* p_s;   cudaGetSymbolAddress(&p_s,   g_scores);
    void* p_p;   cudaGetSymbolAddress(&p_p,   g_p);
    void* p_q;   cudaGetSymbolAddress(&p_q,   g_q);
    void* p_k;   cudaGetSymbolAddress(&p_k,   g_k);
    void* p_o;   cudaGetSymbolAddress(&p_o,   g_o);
    void* p_vt;  cudaGetSymbolAddress(&p_vt,  g_vt);
    void* p_wq;  cudaGetSymbolAddress(&p_wq,  g_wq);
    void* p_wo;  cudaGetSymbolAddress(&p_wo,  g_wo);
    void* p_x;   cudaGetSymbolAddress(&p_x,   g_x);

    cudaFuncSetAttribute(tc_gemm, cudaFuncAttributeMaxDynamicSharedMemorySize, GEMM_SMEM);

    // 0) weight transpose + fp16 rounding; activation rounding
    cvtT_kernel<<<dim3(QKVDIM / 32, DIMM / 32), dim3(32, 8)>>>(Wqkv, (__half*)p_wq, DIMM, QKVDIM);
    cvtT_kernel<<<dim3(DIMM / 32,  DIMM / 32), dim3(32, 8)>>>(Wout, (__half*)p_wo, DIMM, DIMM);
    {
        size_t n4 = (size_t)TOKENS * DIMM / 4;
        cvt_h_kernel<<<(unsigned)((n4 + 255) / 256), 256>>>(x, (__half*)p_x, n4);
    }

    // 1) QKV projection (fp16 MMA, f32 out)
    tc_gemm<<<dim3(TOKENS / 128, QKVDIM / 128, 1), 256, GEMM_SMEM>>>(
        (const __half*)p_x, (const __half*)p_wq, bqkv, p_qkv,
        0, 0, 0, DIMM, DIMM, QKVDIM, DIMM, 1.f, 0);

    // 2) RMSNorm + RoPE (half out), V transpose (half out)
    rmsrope_kernel<<<TOKENS, 256>>>(cosb, sinb, gq, gk);
    vtrans_kernel<<<dim3(LL / 32, HDIM / 32, BB * NHEADS), dim3(32, 8)>>>();

    // 3) scores = SCALE * q k^T (f32 out)
    for (int b = 0; b < BB; b++) {
        tc_gemm<<<dim3(LL / 128, LL / 128, NHEADS), 256, GEMM_SMEM>>>(
            (const __half*)p_q + (size_t)b * LL * DIMM,
            (const __half*)p_k + (size_t)b * LL * DIMM,
            nullptr,
            (float*)p_s + (size_t)b * NHEADS * LL * LL,
            HDIM, HDIM, (long)LL * LL,
            DIMM, DIMM, LL, HDIM, SCALE, 0);
    }

    // 4) softmax -> half probs
    softmax_kernel<<<BB * NHEADS * LL, 256>>>();

    // 5) o = P V (half out)
    for (int b = 0; b < BB; b++) {
        tc_gemm<<<dim3(LL / 128, HDIM / 128, NHEADS), 256, GEMM_SMEM>>>(
            (const __half*)p_p + (size_t)b * NHEADS * LL * LL,
            (const __half*)p_vt + (size_t)b * NHEADS * HDIM * LL,
            nullptr,
            (__half*)p_o + (size_t)b * LL * DIMM,
            (long)LL * LL, (long)HDIM * LL, HDIM,
            LL, LL, DIMM, LL, 1.f, 1);
    }

    // 6) out projection (f32 out to d_out)
    tc_gemm<<<dim3(TOKENS / 128, DIMM / 128, 1), 256, GEMM_SMEM>>>(
        (const __half*)p_o, (const __half*)p_wo, bout, out,
        0, 0, 0, DIMM, DIMM, DIMM, DIMM, 1.f, 0);
}

// round 8
// speedup vs baseline: 8.6215x; 1.1272x over previous
#include <cuda_runtime.h>
#include <cuda_fp16.h>
#include <math.h>
#include <stdint.h>

// Problem constants
#define DIMM 5120
#define NHEADS 40
#define HDIM 128
#define BB 2
#define LL 1024
#define TOKENS (BB*LL)          // 2048
#define QKVDIM (3*DIMM)         // 15360
#define SCALE 0.08838834764831845f
#define EPS 1e-6f

// -------- scratch (static device globals; no runtime allocation) --------
__device__ float  g_qkv[(size_t)TOKENS * QKVDIM];           // 125.8 MB f32
__device__ __half g_q[(size_t)TOKENS * DIMM];               // scaled by SCALE
__device__ __half g_k[(size_t)TOKENS * DIMM];
__device__ __half g_o[(size_t)TOKENS * DIMM];
__device__ __half g_vt[(size_t)BB * NHEADS * HDIM * LL];    // V^T per head
__device__ __half g_wq[(size_t)QKVDIM * DIMM];              // W_qkv^T [N,K]
__device__ __half g_wo[(size_t)DIMM * DIMM];                // W_out^T [N,K]
__device__ __half g_x[(size_t)TOKENS * DIMM];               // x, half

// ============================================================
// helpers
// ============================================================
__device__ __forceinline__ uint32_t smem_u32(const void* p) {
    uint32_t a;
    asm("{ .reg .u64 t; cvta.to.shared.u64 t, %1; cvt.u32.u64 %0, t; }" : "=r"(a) : "l"(p));
    return a;
}
__device__ __forceinline__ void cpa16(uint32_t dst, const void* src) {
    asm volatile("cp.async.cg.shared.global [%0], [%1], 16;" :: "r"(dst), "l"(src));
}
#define CPA_COMMIT() asm volatile("cp.async.commit_group;" ::: "memory")
#define CPA_WAIT1()  asm volatile("cp.async.wait_group 1;" ::: "memory")
#define CPA_WAIT0()  asm volatile("cp.async.wait_group 0;" ::: "memory")

// fp16 m16n8k16, f32 accum
__device__ __forceinline__ void mma16816(float* d, const uint32_t* a, uint32_t b0, uint32_t b1) {
    asm volatile(
        "mma.sync.aligned.m16n8k16.row.col.f32.f16.f16.f32 "
        "{%0,%1,%2,%3}, {%4,%5,%6,%7}, {%8,%9}, {%0,%1,%2,%3};"
        : "+f"(d[0]), "+f"(d[1]), "+f"(d[2]), "+f"(d[3])
        : "r"(a[0]), "r"(a[1]), "r"(a[2]), "r"(a[3]), "r"(b0), "r"(b1));
}
__device__ __forceinline__ void ldsm4(uint32_t* r, uint32_t addr) {
    asm volatile("ldmatrix.sync.aligned.m8n8.x4.shared.b16 {%0,%1,%2,%3}, [%4];"
        : "=r"(r[0]), "=r"(r[1]), "=r"(r[2]), "=r"(r[3]) : "r"(addr));
}
__device__ __forceinline__ uint32_t packh2(float x, float y) {
    __half2 h = __floats2half2_rn(x, y);
    return *(uint32_t*)&h;
}

// ============================================================
// fp16 mma.sync GEMM (unchanged from R7):
//   C[z][m,n] = alpha * A[z][m,:K] * Bt[z][n,:K]^T (+ bias[n])
// ============================================================
#define KC 64
#define ROWB 144
#define TILE_B (128 * ROWB)
#define STAGE_B (2 * TILE_B)
#define NSTG 3
#define GEMM_SMEM (NSTG * STAGE_B)          // 110592 B

__global__ __launch_bounds__(256) void tc_gemm(
    const __half* __restrict__ A, const __half* __restrict__ Bt,
    const float* __restrict__ bias, void* __restrict__ Cv,
    long sAz, long sBz, long sCz,
    int lda, int ldb, int ldc, int K, float alpha, int store_half)
{
    extern __shared__ char sm[];
    const uint32_t sb = smem_u32(sm);

    A  += (size_t)blockIdx.z * sAz;
    Bt += (size_t)blockIdx.z * sBz;

    const int tid  = threadIdx.x;
    const int warp = tid >> 5;
    const int lane = tid & 31;
    const int wm = warp >> 2;
    const int wn = warp & 3;
    const int m0 = blockIdx.x * 128;
    const int n0 = blockIdx.y * 128;

    const uint32_t aOff = (uint32_t)(lane & 15) * ROWB + (uint32_t)(lane >> 4) * 16;
    const uint32_t bOff = (uint32_t)((lane & 7) + ((lane >> 4) & 1) * 8) * ROWB
                        + (uint32_t)((lane >> 3) & 1) * 16;

    float acc[4][4][4];
#pragma unroll
    for (int mt = 0; mt < 4; mt++)
#pragma unroll
        for (int nt = 0; nt < 4; nt++)
#pragma unroll
            for (int r = 0; r < 4; r++) acc[mt][nt][r] = 0.f;

    const int nch = K / KC;

    auto load_chunk = [&](int st, int kc) {
        uint32_t base = sb + (uint32_t)st * STAGE_B;
#pragma unroll
        for (int i = 0; i < 4; i++) {
            int op = tid + i * 256;
            int row = op >> 3, g = op & 7;
            uint32_t off = (uint32_t)row * ROWB + (uint32_t)g * 16;
            cpa16(base + off,
                  (const char*)A + ((size_t)(m0 + row) * lda + kc + g * 8) * 2);
            cpa16(base + TILE_B + off,
                  (const char*)Bt + ((size_t)(n0 + row) * ldb + kc + g * 8) * 2);
        }
    };

    load_chunk(0, 0);       CPA_COMMIT();
    if (nch > 1) { load_chunk(1, KC); CPA_COMMIT(); }

    for (int c = 0; c < nch; c++) {
        const int st = c % NSTG;
        if (c + 1 < nch) { CPA_WAIT1(); } else { CPA_WAIT0(); }
        __syncthreads();
        if (c + 2 < nch) { load_chunk((c + 2) % NSTG, (c + 2) * KC); CPA_COMMIT(); }

        const uint32_t aBase = sb + (uint32_t)st * STAGE_B
                             + (uint32_t)(wm * 64) * ROWB + aOff;
        const uint32_t bBase = sb + (uint32_t)st * STAGE_B + TILE_B
                             + (uint32_t)(wn * 32) * ROWB + bOff;

#pragma unroll
        for (int s = 0; s < 4; s++) {
            const uint32_t kb = (uint32_t)s * 32;
            uint32_t af[4][4];
#pragma unroll
            for (int mt = 0; mt < 4; mt++)
                ldsm4(af[mt], aBase + (uint32_t)(mt * 16) * ROWB + kb);
            uint32_t bf[2][4];
#pragma unroll
            for (int np = 0; np < 2; np++)
                ldsm4(bf[np], bBase + (uint32_t)(np * 16) * ROWB + kb);
#pragma unroll
            for (int mt = 0; mt < 4; mt++)
#pragma unroll
                for (int nt = 0; nt < 4; nt++)
                    mma16816(acc[mt][nt], af[mt],
                             bf[nt >> 1][(nt & 1) * 2], bf[nt >> 1][(nt & 1) * 2 + 1]);
        }
    }

    {
        const int r = lane >> 2, cq = lane & 3;
#pragma unroll
        for (int mt = 0; mt < 4; mt++) {
            int row = m0 + wm * 64 + mt * 16 + r;
#pragma unroll
            for (int nt = 0; nt < 4; nt++) {
                int col = n0 + wn * 32 + nt * 8 + 2 * cq;
                float bvx = 0.f, bvy = 0.f;
                if (bias) { float2 bv = *(const float2*)(bias + col); bvx = bv.x; bvy = bv.y; }
                float o0x = fmaf(acc[mt][nt][0], alpha, bvx);
                float o0y = fmaf(acc[mt][nt][1], alpha, bvy);
                float o1x = fmaf(acc[mt][nt][2], alpha, bvx);
                float o1y = fmaf(acc[mt][nt][3], alpha, bvy);
                if (store_half) {
                    __half* C = (__half*)Cv + (size_t)blockIdx.z * sCz;
                    *(__half2*)(C + (size_t)row * ldc + col) = __floats2half2_rn(o0x, o0y);
                    *(__half2*)(C + (size_t)(row + 8) * ldc + col) = __floats2half2_rn(o1x, o1y);
                } else {
                    float* C = (float*)Cv + (size_t)blockIdx.z * sCz;
                    *(float2*)(C + (size_t)row * ldc + col) = make_float2(o0x, o0y);
                    *(float2*)(C + (size_t)(row + 8) * ldc + col) = make_float2(o1x, o1y);
                }
            }
        }
    }
}

// ============================================================
// Flash attention: one CTA = 128 q rows x one (b,h).
// 8 warps x 16 rows; online softmax; O = softmax(q k^T) V.
// q pre-scaled by SCALE. K tile: [seq128 x d128]; V^T tile: [d128 x seq128].
// 272B smem rows -> conflict-free ldmatrix/cp.async.
// ============================================================
#define FROWB 272
#define FTILE_B (128 * FROWB)               // 34816
#define FLASH_SMEM (5 * FTILE_B)            // 174080: Q + 2x(K+V)

__global__ __launch_bounds__(256, 1) void flash_kernel()
{
    extern __shared__ char sm[];
    const uint32_t sb = smem_u32(sm);
    const int tid = threadIdx.x, warp = tid >> 5, lane = tid & 31;
    const int bh = blockIdx.y;
    const int b = bh / NHEADS, h = bh % NHEADS;
    const int q0 = blockIdx.x * 128;

    const char* Qg = (const char*)(g_q + ((size_t)(b * LL + q0)) * DIMM + h * HDIM);
    const char* Kg = (const char*)(g_k + ((size_t)(b * LL)) * DIMM + h * HDIM);
    const char* Vg = (const char*)(g_vt + (size_t)bh * HDIM * LL);

    const uint32_t aOff = (uint32_t)(lane & 15) * FROWB + (uint32_t)(lane >> 4) * 16;
    const uint32_t bOff = (uint32_t)((lane & 7) + ((lane >> 4) & 1) * 8) * FROWB
                        + (uint32_t)((lane >> 3) & 1) * 16;

    // granule mapping: 2048 granules / 256 thr = 8 per thread; 16 per row
    const int grow = tid >> 1;  (void)grow;

    auto load_kv = [&](int st, int j) {
        uint32_t kb = sb + FTILE_B + (uint32_t)st * (2 * FTILE_B);
        uint32_t vb = kb + FTILE_B;
#pragma unroll
        for (int i = 0; i < 8; i++) {
            int op = tid + i * 256;
            int row = op >> 4, g = op & 15;
            uint32_t off = (uint32_t)row * FROWB + (uint32_t)g * 16;
            cpa16(kb + off, Kg + ((size_t)(j * 128 + row) * DIMM) * 2 + g * 16);
            cpa16(vb + off, Vg + ((size_t)row * LL + j * 128) * 2 + g * 16);
        }
    };

    // prologue: Q tile + KV block 0
    {
#pragma unroll
        for (int i = 0; i < 8; i++) {
            int op = tid + i * 256;
            int row = op >> 4, g = op & 15;
            cpa16(sb + (uint32_t)row * FROWB + (uint32_t)g * 16,
                  Qg + (size_t)row * DIMM * 2 + g * 16);
        }
        CPA_COMMIT();
        load_kv(0, 0); CPA_COMMIT();
        CPA_WAIT1();            // Q resident (oldest group retires first)
        __syncthreads();
    }

    // Q fragments: 16 rows x 128 d, 8 k16 steps
    uint32_t aq[8][4];
    {
        uint32_t qBase = sb + (uint32_t)(warp * 16) * FROWB + aOff;
#pragma unroll
        for (int kk = 0; kk < 8; kk++)
            ldsm4(aq[kk], qBase + (uint32_t)kk * 32);
    }

    float accO[16][4];
#pragma unroll
    for (int nt = 0; nt < 16; nt++)
#pragma unroll
        for (int r = 0; r < 4; r++) accO[nt][r] = 0.f;
    float m0 = -1e30f, m1 = -1e30f, l0 = 0.f, l1 = 0.f;

    for (int j = 0; j < 8; j++) {
        const int st = j & 1;
        CPA_WAIT0();
        __syncthreads();
        if (j + 1 < 8) { load_kv((j + 1) & 1, j + 1); CPA_COMMIT(); }

        const uint32_t kBase = sb + FTILE_B + (uint32_t)st * (2 * FTILE_B) + bOff;
        const uint32_t vBase = kBase + FTILE_B;

        // S = q k^T (16 x 128), f32 accum
        float sA[16][4];
#pragma unroll
        for (int nt = 0; nt < 16; nt++)
#pragma unroll
            for (int r = 0; r < 4; r++) sA[nt][r] = 0.f;
#pragma unroll
        for (int kk = 0; kk < 8; kk++) {
#pragma unroll
            for (int np = 0; np < 8; np++) {
                uint32_t bf[4];
                ldsm4(bf, kBase + (uint32_t)(np * 16) * FROWB + (uint32_t)kk * 32);
                mma16816(sA[2 * np],     aq[kk], bf[0], bf[1]);
                mma16816(sA[2 * np + 1], aq[kk], bf[2], bf[3]);
            }
        }

        // online softmax (rows r, r+8 per lane)
        float mx0 = -1e30f, mx1 = -1e30f;
#pragma unroll
        for (int nt = 0; nt < 16; nt++) {
            mx0 = fmaxf(mx0, fmaxf(sA[nt][0], sA[nt][1]));
            mx1 = fmaxf(mx1, fmaxf(sA[nt][2], sA[nt][3]));
        }
        mx0 = fmaxf(mx0, __shfl_xor_sync(0xffffffffu, mx0, 1));
        mx0 = fmaxf(mx0, __shfl_xor_sync(0xffffffffu, mx0, 2));
        mx1 = fmaxf(mx1, __shfl_xor_sync(0xffffffffu, mx1, 1));
        mx1 = fmaxf(mx1, __shfl_xor_sync(0xffffffffu, mx1, 2));
        float mn0 = fmaxf(m0, mx0), mn1 = fmaxf(m1, mx1);
        float c0 = __expf(m0 - mn0), c1 = __expf(m1 - mn1);
        l0 *= c0; l1 *= c1;
#pragma unroll
        for (int nt = 0; nt < 16; nt++) {
            accO[nt][0] *= c0; accO[nt][1] *= c0;
            accO[nt][2] *= c1; accO[nt][3] *= c1;
        }
        float s0 = 0.f, s1 = 0.f;
        uint32_t pa0[16], pa1[16];
#pragma unroll
        for (int nt = 0; nt < 16; nt++) {
            float p0 = __expf(sA[nt][0] - mn0);
            float p1 = __expf(sA[nt][1] - mn0);
            float p2 = __expf(sA[nt][2] - mn1);
            float p3 = __expf(sA[nt][3] - mn1);
            s0 += p0 + p1; s1 += p2 + p3;
            pa0[nt] = packh2(p0, p1);
            pa1[nt] = packh2(p2, p3);
        }
        s0 += __shfl_xor_sync(0xffffffffu, s0, 1);
        s0 += __shfl_xor_sync(0xffffffffu, s0, 2);
        s1 += __shfl_xor_sync(0xffffffffu, s1, 1);
        s1 += __shfl_xor_sync(0xffffffffu, s1, 2);
        l0 += s0; l1 += s1; m0 = mn0; m1 = mn1;

        // O += P V  (k over 128 seq = 8 k16 steps)
#pragma unroll
        for (int kk = 0; kk < 8; kk++) {
            uint32_t a[4] = { pa0[2 * kk], pa1[2 * kk], pa0[2 * kk + 1], pa1[2 * kk + 1] };
#pragma unroll
            for (int np = 0; np < 8; np++) {
                uint32_t bf[4];
                ldsm4(bf, vBase + (uint32_t)(np * 16) * FROWB + (uint32_t)kk * 32);
                mma16816(accO[2 * np],     a, bf[0], bf[1]);
                mma16816(accO[2 * np + 1], a, bf[2], bf[3]);
            }
        }
    }

    // epilogue: O /= l, write half
    {
        float i0 = 1.f / l0, i1 = 1.f / l1;
        const int r = lane >> 2, cq = lane & 3;
        __half* Og = g_o + ((size_t)(b * LL + q0 + warp * 16)) * DIMM + h * HDIM;
#pragma unroll
        for (int nt = 0; nt < 16; nt++) {
            int col = nt * 8 + 2 * cq;
            *(__half2*)(Og + (size_t)r * DIMM + col) =
                __floats2half2_rn(accO[nt][0] * i0, accO[nt][1] * i0);
            *(__half2*)(Og + (size_t)(r + 8) * DIMM + col) =
                __floats2half2_rn(accO[nt][2] * i1, accO[nt][3] * i1);
        }
    }
}

// ============================================================
// convert helpers
// ============================================================
__global__ void cvt_h_kernel(const float* __restrict__ s, __half* __restrict__ d, size_t n4)
{
    size_t i = (size_t)blockIdx.x * blockDim.x + threadIdx.x;
    if (i < n4) {
        float4 v = ((const float4*)s)[i];
        ((__half2*)d)[2 * i]     = __floats2half2_rn(v.x, v.y);
        ((__half2*)d)[2 * i + 1] = __floats2half2_rn(v.z, v.w);
    }
}

__global__ void cvtT_kernel(const float* __restrict__ src, __half* __restrict__ dst,
                            int K, int N)
{
    __shared__ float tile[32][33];
    int k0 = blockIdx.y * 32, n0 = blockIdx.x * 32;
    int tx = threadIdx.x, ty = threadIdx.y;
#pragma unroll
    for (int i = 0; i < 32; i += 8)
        tile[ty + i][tx] = src[(size_t)(k0 + ty + i) * N + n0 + tx];
    __syncthreads();
#pragma unroll
    for (int i = 0; i < 32; i += 8)
        dst[(size_t)(n0 + ty + i) * K + k0 + tx] = __float2half_rn(tile[tx][ty + i]);
}

// V^T per head
__global__ void vtrans_kernel()
{
    __shared__ float tile[32][33];
    const int bh = blockIdx.z;
    const int b = bh / NHEADS, h = bh % NHEADS;
    const int k0 = blockIdx.x * 32, d0 = blockIdx.y * 32;
    const float* src = g_qkv + (size_t)b * LL * QKVDIM + 2 * DIMM + h * HDIM;
    __half* dst = g_vt + (size_t)bh * HDIM * LL;
    int tx = threadIdx.x, ty = threadIdx.y;
#pragma unroll
    for (int i = 0; i < 32; i += 8)
        tile[ty + i][tx] = src[(size_t)(k0 + ty + i) * QKVDIM + d0 + tx];
    __syncthreads();
#pragma unroll
    for (int i = 0; i < 32; i += 8)
        dst[(size_t)(d0 + ty + i) * LL + k0 + tx] = __float2half_rn(tile[tx][ty + i]);
}

// ============================================================
// RMSNorm + gain + RoPE -> half q (pre-scaled by SCALE), k
// ============================================================
__global__ __launch_bounds__(256) void rmsrope_kernel(
    const float* __restrict__ cosb, const float* __restrict__ sinb,
    const float* __restrict__ gq, const float* __restrict__ gk)
{
    const int t = blockIdx.x;
    const int tid = threadIdx.x;
    const float* base = g_qkv + (size_t)t * QKVDIM;

    float sq = 0.f, sk = 0.f;
    for (int i = tid; i < DIMM; i += 256) {
        float a = base[i];         sq = fmaf(a, a, sq);
        float b = base[DIMM + i];  sk = fmaf(b, b, sk);
    }
    __shared__ float r1[256], r2[256];
    r1[tid] = sq; r2[tid] = sk;
    __syncthreads();
    for (int s = 128; s > 0; s >>= 1) {
        if (tid < s) { r1[tid] += r1[tid + s]; r2[tid] += r2[tid + s]; }
        __syncthreads();
    }
    const float rq = rsqrtf(r1[0] / (float)DIMM + EPS);
    const float rk = rsqrtf(r2[0] / (float)DIMM + EPS);

    const int l = t & (LL - 1);
    const float* cl = cosb + (size_t)l * HDIM;
    const float* sl = sinb + (size_t)l * HDIM;
    __half* qo = g_q + (size_t)t * DIMM;
    __half* ko = g_k + (size_t)t * DIMM;

    for (int p = tid; p < DIMM / 2; p += 256) {
        int d = 2 * p;
        int hd = d & (HDIM - 1);
        float c = cl[hd];
        float s = sl[hd + 1];
        float x0 = base[d]     * rq * gq[d];
        float x1 = base[d + 1] * rq * gq[d + 1];
        *(__half2*)(qo + d) = __floats2half2_rn((x0 * c - x1 * s) * SCALE,
                                                (x0 * s + x1 * c) * SCALE);
        float y0 = base[DIMM + d]     * rk * gk[d];
        float y1 = base[DIMM + d + 1] * rk * gk[d + 1];
        *(__half2*)(ko + d) = __floats2half2_rn(y0 * c - y1 * s, y0 * s + y1 * c);
    }
}

// ============================================================
// launch
// ============================================================
extern "C" void kernel_launch(void* const* d_in, const int* in_sizes, int n_in,
                              void* d_out, int out_size)
{
    const float* x     = (const float*)d_in[0];
    const float* cosb  = (const float*)d_in[1];
    const float* sinb  = (const float*)d_in[2];
    const float* Wqkv  = (const float*)d_in[3];
    const float* bqkv  = (const float*)d_in[4];
    const float* gq    = (const float*)d_in[5];
    const float* gk    = (const float*)d_in[6];
    const float* Wout  = (const float*)d_in[7];
    const float* bout  = (const float*)d_in[8];
    float* out = (float*)d_out;

    void* p_qkv; cudaGetSymbolAddress(&p_qkv, g_qkv);
    void* p_o;   cudaGetSymbolAddress(&p_o,   g_o);
    void* p_wq;  cudaGetSymbolAddress(&p_wq,  g_wq);
    void* p_wo;  cudaGetSymbolAddress(&p_wo,  g_wo);
    void* p_x;   cudaGetSymbolAddress(&p_x,   g_x);

    cudaFuncSetAttribute(tc_gemm, cudaFuncAttributeMaxDynamicSharedMemorySize, GEMM_SMEM);
    cudaFuncSetAttribute(flash_kernel, cudaFuncAttributeMaxDynamicSharedMemorySize, FLASH_SMEM);

    // 0) weight transpose + fp16 rounding; activation rounding
    cvtT_kernel<<<dim3(QKVDIM / 32, DIMM / 32), dim3(32, 8)>>>(Wqkv, (__half*)p_wq, DIMM, QKVDIM);
    cvtT_kernel<<<dim3(DIMM / 32,  DIMM / 32), dim3(32, 8)>>>(Wout, (__half*)p_wo, DIMM, DIMM);
    {
        size_t n4 = (size_t)TOKENS * DIMM / 4;
        cvt_h_kernel<<<(unsigned)((n4 + 255) / 256), 256>>>(x, (__half*)p_x, n4);
    }

    // 1) QKV projection (fp16 MMA, f32 out)
    tc_gemm<<<dim3(TOKENS / 128, QKVDIM / 128, 1), 256, GEMM_SMEM>>>(
        (const __half*)p_x, (const __half*)p_wq, bqkv, p_qkv,
        0, 0, 0, DIMM, DIMM, QKVDIM, DIMM, 1.f, 0);

    // 2) RMSNorm + RoPE (half out, q pre-scaled), V transpose (half out)
    rmsrope_kernel<<<TOKENS, 256>>>(cosb, sinb, gq, gk);
    vtrans_kernel<<<dim3(LL / 32, HDIM / 32, BB * NHEADS), dim3(32, 8)>>>();

    // 3) fused attention: scores + softmax + PV
    flash_kernel<<<dim3(LL / 128, BB * NHEADS), 256, FLASH_SMEM>>>();

    // 4) out projection (f32 out to d_out)
    tc_gemm<<<dim3(TOKENS / 128, DIMM / 128, 1), 256, GEMM_SMEM>>>(
        (const __half*)p_o, (const __half*)p_wo, bout, out,
        0, 0, 0, DIMM, DIMM, DIMM, DIMM, 1.f, 0);
}